// round 1
// baseline (speedup 1.0000x reference)
#include <cuda_runtime.h>
#include <math.h>

#define Bsz   8
#define Cch   256
#define Lseq  1024
#define Mtok  8192      // Bsz*Lseq
#define DIdim 512
#define DSdim 16
#define NLAYER 4

// ---------------- scratch (device globals: no allocations allowed) ----------
__device__ float g_xs  [Mtok*Cch];        // running activations (b,l,c)
__device__ float g_xn  [Mtok*Cch];        // layernorm output
__device__ float g_xz  [Mtok*2*DIdim];    // in_proj output: [:,0:512)=xin, [:,512:1024)=z
__device__ float g_xc  [Mtok*DIdim];      // conv+silu output
__device__ float g_proj[Mtok*48];         // x_proj output (dtr|B|C)
__device__ float g_dt  [Mtok*DIdim];      // softplus(dt)
__device__ float g_y   [Mtok*DIdim];      // scan output / gated
__device__ float g_g0  [Bsz*Cch];         // SE pooled
__device__ float g_gate[Bsz*Cch];         // SE sigmoid gate
__device__ float g_ybn [Bsz*Cch*Lseq];    // pre-BN output (b,c,l)
__device__ float g_stats[2*Cch];          // BN mu, rstd

// ---------------- helpers ----------------------------------------------------
__device__ __forceinline__ float siluf(float v) { return v / (1.f + __expf(-v)); }

// ---------------- input transpose (b,c,l) -> (b,l,c) -------------------------
__global__ void k_transpose_in(const float* __restrict__ x) {
    __shared__ float tile[32][33];
    int b = blockIdx.z, c0 = blockIdx.y * 32, l0 = blockIdx.x * 32;
    int tx = threadIdx.x, ty = threadIdx.y;
    #pragma unroll
    for (int i = ty; i < 32; i += 8)
        tile[i][tx] = x[(size_t)(b*Cch + c0 + i)*Lseq + l0 + tx];
    __syncthreads();
    #pragma unroll
    for (int i = ty; i < 32; i += 8)
        g_xs[(size_t)(b*Lseq + l0 + i)*Cch + c0 + tx] = tile[tx][i];
}

// ---------------- layernorm over C per token ---------------------------------
__global__ void k_ln(const float* __restrict__ w, const float* __restrict__ bias) {
    int m = blockIdx.x;
    int c = threadIdx.x;                     // 256 threads
    float v = g_xs[(size_t)m*Cch + c];
    __shared__ float sh[256], sh2[256];
    sh[c] = v; sh2[c] = v * v;
    __syncthreads();
    #pragma unroll
    for (int st = 128; st > 0; st >>= 1) {
        if (c < st) { sh[c] += sh[c + st]; sh2[c] += sh2[c + st]; }
        __syncthreads();
    }
    float mu  = sh[0] * (1.f/256.f);
    float var = sh2[0] * (1.f/256.f) - mu*mu;
    g_xn[(size_t)m*Cch + c] = (v - mu) * rsqrtf(var + 1e-5f) * w[c] + bias[c];
}

// ---------------- fp32 GEMM: C[M,N] (+)= A[M,K] @ W[N,K]^T -------------------
// BM=128, BN=64, BK=16, 256 threads, 8x4 microtile. M multiple of 128, K of 16.
template<bool ACC>
__launch_bounds__(256)
__global__ void k_gemm(const float* __restrict__ A, const float* __restrict__ W,
                       float* __restrict__ Cout, int N, int Kd)
{
    __shared__ float As[16][132];
    __shared__ float Bs[16][68];
    const int m0 = blockIdx.y * 128, n0 = blockIdx.x * 64;
    const int tid = threadIdx.x;
    const int tx = tid & 15, ty = tid >> 4;
    const int ar = tid >> 2;            // 0..63
    const int ac = (tid & 3) << 2;      // 0,4,8,12

    float acc[8][4];
    #pragma unroll
    for (int i = 0; i < 8; i++)
        #pragma unroll
        for (int j = 0; j < 4; j++) acc[i][j] = 0.f;

    for (int k0 = 0; k0 < Kd; k0 += 16) {
        float4 a0 = *(const float4*)(A + (size_t)(m0 + ar)      * Kd + k0 + ac);
        float4 a1 = *(const float4*)(A + (size_t)(m0 + ar + 64) * Kd + k0 + ac);
        float4 b0 = make_float4(0.f, 0.f, 0.f, 0.f);
        if (n0 + ar < N) b0 = *(const float4*)(W + (size_t)(n0 + ar) * Kd + k0 + ac);
        As[ac+0][ar] = a0.x; As[ac+1][ar] = a0.y; As[ac+2][ar] = a0.z; As[ac+3][ar] = a0.w;
        As[ac+0][ar+64] = a1.x; As[ac+1][ar+64] = a1.y; As[ac+2][ar+64] = a1.z; As[ac+3][ar+64] = a1.w;
        Bs[ac+0][ar] = b0.x; Bs[ac+1][ar] = b0.y; Bs[ac+2][ar] = b0.z; Bs[ac+3][ar] = b0.w;
        __syncthreads();
        #pragma unroll
        for (int kk = 0; kk < 16; kk++) {
            float4 av0 = *(const float4*)&As[kk][ty*8];
            float4 av1 = *(const float4*)&As[kk][ty*8 + 4];
            float4 bv  = *(const float4*)&Bs[kk][tx*4];
            float a[8] = {av0.x, av0.y, av0.z, av0.w, av1.x, av1.y, av1.z, av1.w};
            float bb[4] = {bv.x, bv.y, bv.z, bv.w};
            #pragma unroll
            for (int i = 0; i < 8; i++)
                #pragma unroll
                for (int j = 0; j < 4; j++)
                    acc[i][j] = fmaf(a[i], bb[j], acc[i][j]);
        }
        __syncthreads();
    }
    #pragma unroll
    for (int i = 0; i < 8; i++) {
        int m = m0 + ty*8 + i;
        int nb = n0 + tx*4;
        #pragma unroll
        for (int j = 0; j < 4; j++) {
            int n = nb + j;
            if (n < N) {
                size_t o = (size_t)m * N + n;
                Cout[o] = ACC ? (Cout[o] + acc[i][j]) : acc[i][j];
            }
        }
    }
}

// ---------------- depthwise causal conv (K=4) + silu -------------------------
__global__ void k_conv(const float* __restrict__ w, const float* __restrict__ bias) {
    int idx = blockIdx.x * 256 + threadIdx.x;      // over Mtok*DIdim
    int d = idx & (DIdim - 1);
    int m = idx >> 9;
    int l = m & (Lseq - 1);
    float s = bias[d];
    const float* wd = w + d*4;
    #pragma unroll
    for (int k = 0; k < 4; k++) {
        int ls = l - 3 + k;
        if (ls >= 0) s += wd[k] * g_xz[(size_t)(m - 3 + k)*(2*DIdim) + d];
    }
    g_xc[idx] = siluf(s);
}

// ---------------- dt projection + softplus (K=16 tiny GEMM) ------------------
__global__ void k_dt(const float* __restrict__ dw, const float* __restrict__ db) {
    int m = blockIdx.x;
    int d = threadIdx.x;                 // 512 threads
    __shared__ float p[16];
    if (d < 16) p[d] = g_proj[(size_t)m*48 + d];
    __syncthreads();
    float s = db[d];
    #pragma unroll
    for (int r = 0; r < 16; r++) s += p[r] * dw[d*16 + r];
    g_dt[(size_t)m*DIdim + d] = (s > 20.f) ? s : log1pf(__expf(s));
}

// ---------------- selective scan --------------------------------------------
// block: 256 thr = 16 channels (dg) x 16 states (n). grid: Bsz * DIdim/16 = 256.
// dt/x/B/C staged through shared in 64-step double-buffered chunks.
__launch_bounds__(256)
__global__ void k_scan(const float* __restrict__ alog, const float* __restrict__ Dp) {
    __shared__ float s_dt[2][64][16];
    __shared__ float s_x [2][64][16];
    __shared__ float s_B [2][64][16];
    __shared__ float s_C [2][64][16];
    int b  = blockIdx.x >> 5;
    int d0 = (blockIdx.x & 31) << 4;
    int tid = threadIdx.x;
    int n  = tid & 15, dg = tid >> 4;
    int d  = d0 + dg;
    float Ad = -__expf(alog[d*DSdim + n]);
    float Dv = Dp[d];
    float h = 0.f;
    float rdt[4], rx[4], rB[4], rC[4];

    auto ldc = [&](int l0) {
        #pragma unroll
        for (int it = 0; it < 4; it++) {
            int i = tid + it*256;
            int l = i >> 4, j = i & 15;
            size_t t = (size_t)(b*Lseq + l0 + l);
            rdt[it] = g_dt[t*DIdim + d0 + j];
            rx[it]  = g_xc[t*DIdim + d0 + j];
            rB[it]  = g_proj[t*48 + 16 + j];
            rC[it]  = g_proj[t*48 + 32 + j];
        }
    };
    auto stc = [&](int buf) {
        #pragma unroll
        for (int it = 0; it < 4; it++) {
            int i = tid + it*256;
            int l = i >> 4, j = i & 15;
            s_dt[buf][l][j] = rdt[it]; s_x[buf][l][j] = rx[it];
            s_B [buf][l][j] = rB [it]; s_C[buf][l][j] = rC[it];
        }
    };

    ldc(0); stc(0); __syncthreads();
    for (int ch = 0; ch < 16; ch++) {
        int buf = ch & 1;
        if (ch < 15) ldc((ch + 1) * 64);    // prefetch next chunk into regs
        #pragma unroll 4
        for (int l = 0; l < 64; l++) {
            float dtv = s_dt[buf][l][dg];
            float xv  = s_x [buf][l][dg];
            float Bv  = s_B [buf][l][n];
            float Cv  = s_C [buf][l][n];
            h = h * __expf(dtv * Ad) + (dtv * xv) * Bv;
            float p = h * Cv;
            p += __shfl_xor_sync(0xffffffffu, p, 8, 16);
            p += __shfl_xor_sync(0xffffffffu, p, 4, 16);
            p += __shfl_xor_sync(0xffffffffu, p, 2, 16);
            p += __shfl_xor_sync(0xffffffffu, p, 1, 16);
            if (n == 0)
                g_y[(size_t)(b*Lseq + ch*64 + l)*DIdim + d] = p + xv * Dv;
        }
        __syncthreads();
        if (ch < 15) stc(buf ^ 1);
        __syncthreads();
    }
}

// ---------------- gate: y *= silu(z) -----------------------------------------
__global__ void k_gate() {
    int idx = blockIdx.x * 256 + threadIdx.x;   // Mtok*DIdim
    int m = idx >> 9, d = idx & 511;
    float z = g_xz[(size_t)m*(2*DIdim) + DIdim + d];
    g_y[idx] *= siluf(z);
}

// ---------------- SE: zero, pool, MLP ----------------------------------------
__global__ void k_zero_g0() {
    int i = blockIdx.x * 256 + threadIdx.x;
    if (i < Bsz*Cch) g_g0[i] = 0.f;
}
__global__ void k_pool() {
    int b = blockIdx.x >> 2, q = blockIdx.x & 3;
    int c = threadIdx.x;
    float s = 0.f;
    for (int l = q*256; l < q*256 + 256; l++)
        s += g_xs[(size_t)(b*Lseq + l)*Cch + c];
    atomicAdd(&g_g0[b*Cch + c], s * (1.f/1024.f));
}
__global__ void k_se(const float* __restrict__ w1, const float* __restrict__ b1,
                     const float* __restrict__ w2, const float* __restrict__ b2) {
    __shared__ float sg[Bsz*Cch];
    __shared__ float sh[Bsz*64];
    int t = threadIdx.x;
    for (int i = t; i < Bsz*Cch; i += 256) sg[i] = g_g0[i];
    __syncthreads();
    for (int i = t; i < Bsz*64; i += 256) {
        int b = i >> 6, j = i & 63;
        float s = b1[j];
        const float* wr = w1 + j*256;
        const float* gr = sg + b*256;
        #pragma unroll 8
        for (int c = 0; c < 256; c++) s += gr[c] * wr[c];
        sh[i] = fmaxf(s, 0.f);
    }
    __syncthreads();
    for (int i = t; i < Bsz*Cch; i += 256) {
        int b = i >> 8, c = i & 255;
        float s = b2[c];
        const float* wr = w2 + c*64;
        const float* hr = sh + b*64;
        #pragma unroll 8
        for (int j = 0; j < 64; j++) s += hr[j] * wr[j];
        g_gate[i] = 1.f / (1.f + __expf(-s));
    }
}

// ---------------- y = xo*g + residual, transposed to (b,c,l) -----------------
__global__ void k_ybn(const float* __restrict__ x) {
    __shared__ float tile[32][33];
    int b = blockIdx.z, c0 = blockIdx.y * 32, l0 = blockIdx.x * 32;
    int tx = threadIdx.x, ty = threadIdx.y;
    #pragma unroll
    for (int i = ty; i < 32; i += 8)
        tile[i][tx] = g_xs[(size_t)(b*Lseq + l0 + i)*Cch + c0 + tx];   // tile[l][c]
    __syncthreads();
    #pragma unroll
    for (int i = ty; i < 32; i += 8) {
        int c = c0 + i;
        size_t o = (size_t)(b*Cch + c)*Lseq + l0 + tx;
        g_ybn[o] = tile[tx][i] * g_gate[b*Cch + c] + x[o];
    }
}

// ---------------- batchnorm stats + apply ------------------------------------
__global__ void k_bnstats() {
    int c = blockIdx.x, t = threadIdx.x;
    float s = 0.f, s2 = 0.f;
    for (int b = 0; b < Bsz; b++)
        for (int l = t; l < Lseq; l += 256) {
            float v = g_ybn[(size_t)(b*Cch + c)*Lseq + l];
            s += v; s2 += v * v;
        }
    __shared__ float sh[256], sh2[256];
    sh[t] = s; sh2[t] = s2;
    __syncthreads();
    #pragma unroll
    for (int st = 128; st > 0; st >>= 1) {
        if (t < st) { sh[t] += sh[t + st]; sh2[t] += sh2[t + st]; }
        __syncthreads();
    }
    if (t == 0) {
        float mu  = sh[0] * (1.f/8192.f);
        float var = sh2[0] * (1.f/8192.f) - mu*mu;
        g_stats[c]       = mu;
        g_stats[Cch + c] = rsqrtf(var + 1e-5f);
    }
}
__global__ void k_bnapply(float* __restrict__ out, const float* __restrict__ bw,
                          const float* __restrict__ bb) {
    int idx = blockIdx.x * 256 + threadIdx.x;   // Bsz*Cch*Lseq
    int c = (idx >> 10) & 255;
    out[idx] = (g_ybn[idx] - g_stats[c]) * g_stats[Cch + c] * bw[c] + bb[c];
}

// ---------------- host driver ------------------------------------------------
extern "C" void kernel_launch(void* const* d_in, const int* in_sizes, int n_in,
                              void* d_out, int out_size)
{
    const float* x         = (const float*)d_in[0];
    const float* ln_w      = (const float*)d_in[1];
    const float* ln_b      = (const float*)d_in[2];
    const float* in_proj_w = (const float*)d_in[3];
    const float* conv_w    = (const float*)d_in[4];
    const float* conv_b    = (const float*)d_in[5];
    const float* x_proj_w  = (const float*)d_in[6];
    const float* dt_proj_w = (const float*)d_in[7];
    const float* dt_proj_b = (const float*)d_in[8];
    const float* A_log     = (const float*)d_in[9];
    const float* Dp        = (const float*)d_in[10];
    const float* out_proj_w= (const float*)d_in[11];
    const float* se_w1     = (const float*)d_in[12];
    const float* se_b1     = (const float*)d_in[13];
    const float* se_w2     = (const float*)d_in[14];
    const float* se_b2     = (const float*)d_in[15];
    const float* bn_w      = (const float*)d_in[16];
    const float* bn_b      = (const float*)d_in[17];
    float* out = (float*)d_out;

    void *p;
    cudaGetSymbolAddress(&p, g_xn);   float* pxn   = (float*)p;
    cudaGetSymbolAddress(&p, g_xz);   float* pxz   = (float*)p;
    cudaGetSymbolAddress(&p, g_xc);   float* pxc   = (float*)p;
    cudaGetSymbolAddress(&p, g_proj); float* pproj = (float*)p;
    cudaGetSymbolAddress(&p, g_y);    float* py    = (float*)p;
    cudaGetSymbolAddress(&p, g_xs);   float* pxs   = (float*)p;

    dim3 tb(32, 8);
    k_transpose_in<<<dim3(32, 8, Bsz), tb>>>(x);

    for (int i = 0; i < NLAYER; i++) {
        k_ln<<<Mtok, 256>>>(ln_w + i*Cch, ln_b + i*Cch);
        k_gemm<false><<<dim3(16, 64), 256>>>(pxn, in_proj_w + (size_t)i*1024*256, pxz, 1024, 256);
        k_conv<<<Mtok*DIdim/256, 256>>>(conv_w + i*DIdim*4, conv_b + i*DIdim);
        k_gemm<false><<<dim3(1, 64), 256>>>(pxc, x_proj_w + (size_t)i*48*512, pproj, 48, 512);
        k_dt<<<Mtok, 512>>>(dt_proj_w + i*DIdim*16, dt_proj_b + i*DIdim);
        k_scan<<<256, 256>>>(A_log + i*DIdim*DSdim, Dp + i*DIdim);
        k_gate<<<Mtok*DIdim/256, 256>>>();
        k_gemm<true><<<dim3(4, 64), 256>>>(py, out_proj_w + (size_t)i*256*512, pxs, 256, 512);
    }

    k_zero_g0<<<8, 256>>>();
    k_pool<<<Bsz*4, 256>>>();
    k_se<<<1, 256>>>(se_w1, se_b1, se_w2, se_b2);
    k_ybn<<<dim3(32, 8, Bsz), tb>>>(x);
    k_bnstats<<<Cch, 256>>>();
    k_bnapply<<<Bsz*Cch*Lseq/256, 256>>>(out, bn_w, bn_b);

    (void)in_sizes; (void)n_in; (void)out_size;
}

// round 2
// speedup vs baseline: 1.2769x; 1.2769x over previous
#include <cuda_runtime.h>
#include <math.h>

#define Bsz   8
#define Cch   256
#define Lseq  1024
#define Mtok  8192      // Bsz*Lseq
#define DIdim 512
#define DSdim 16
#define NLAYER 4

// ---------------- scratch (device globals: no allocations allowed) ----------
__device__ float g_xs  [Mtok*Cch];        // running activations (b,l,c)
__device__ float g_xn  [Mtok*Cch];        // layernorm output
__device__ float g_xz  [Mtok*2*DIdim];    // in_proj output: [:,0:512)=xin, [:,512:1024)=z
__device__ float g_xc  [Mtok*DIdim];      // conv+silu output
__device__ float g_proj[Mtok*48];         // x_proj output (dtr|B|C)
__device__ float g_dt  [Mtok*DIdim];      // softplus(dt)
__device__ float g_y   [Mtok*DIdim];      // scan output / gated
__device__ float g_g0  [Bsz*Cch];         // SE pooled
__device__ float g_gate[Bsz*Cch];         // SE sigmoid gate
__device__ float g_ybn [Bsz*Cch*Lseq];    // pre-BN output (b,c,l)
__device__ float g_stats[2*Cch];          // BN mu, rstd

// ---------------- helpers ----------------------------------------------------
__device__ __forceinline__ float siluf(float v) { return v / (1.f + __expf(-v)); }

__device__ __forceinline__ unsigned f2tf32(float x) {
    unsigned r;
    asm("cvt.rna.tf32.f32 %0, %1;" : "=r"(r) : "f"(x));
    return r;
}

__device__ __forceinline__ void mma_tf32(float* d, const unsigned* a, const unsigned* b) {
    asm volatile(
        "mma.sync.aligned.m16n8k8.row.col.f32.tf32.tf32.f32 "
        "{%0,%1,%2,%3}, {%4,%5,%6,%7}, {%8,%9}, {%0,%1,%2,%3};"
        : "+f"(d[0]), "+f"(d[1]), "+f"(d[2]), "+f"(d[3])
        : "r"(a[0]), "r"(a[1]), "r"(a[2]), "r"(a[3]), "r"(b[0]), "r"(b[1]));
}

// ---------------- input transpose (b,c,l) -> (b,l,c) -------------------------
__global__ void k_transpose_in(const float* __restrict__ x) {
    __shared__ float tile[32][33];
    int b = blockIdx.z, c0 = blockIdx.y * 32, l0 = blockIdx.x * 32;
    int tx = threadIdx.x, ty = threadIdx.y;
    #pragma unroll
    for (int i = ty; i < 32; i += 8)
        tile[i][tx] = x[(size_t)(b*Cch + c0 + i)*Lseq + l0 + tx];
    __syncthreads();
    #pragma unroll
    for (int i = ty; i < 32; i += 8)
        g_xs[(size_t)(b*Lseq + l0 + i)*Cch + c0 + tx] = tile[tx][i];
}

// ---------------- layernorm over C per token ---------------------------------
__global__ void k_ln(const float* __restrict__ w, const float* __restrict__ bias) {
    int m = blockIdx.x;
    int c = threadIdx.x;                     // 256 threads
    float v = g_xs[(size_t)m*Cch + c];
    __shared__ float sh[256], sh2[256];
    sh[c] = v; sh2[c] = v * v;
    __syncthreads();
    #pragma unroll
    for (int st = 128; st > 0; st >>= 1) {
        if (c < st) { sh[c] += sh[c + st]; sh2[c] += sh2[c + st]; }
        __syncthreads();
    }
    float mu  = sh[0] * (1.f/256.f);
    float var = sh2[0] * (1.f/256.f) - mu*mu;
    g_xn[(size_t)m*Cch + c] = (v - mu) * rsqrtf(var + 1e-5f) * w[c] + bias[c];
}

// ---------------- tf32 tensor-core GEMM: C[M,N] (+)= A[M,K] @ W[N,K]^T -------
// BM=128, BN=64, BK=32, 256 threads (8 warps: 4 along M x 2 along N),
// warp tile 32x32 = 2x4 m16n8k8 fragments. M % 128 == 0, K % 32 == 0, N even.
template<bool ACC>
__launch_bounds__(256)
__global__ void k_gemm_tc(const float* __restrict__ A, const float* __restrict__ W,
                          float* __restrict__ Cout, int N, int Kd)
{
    __shared__ unsigned As[128][36];   // [m][k] padded: frag LDS conflict-free
    __shared__ unsigned Bs[64][36];    // [n][k]
    const int m0 = blockIdx.y * 128, n0 = blockIdx.x * 64;
    const int tid  = threadIdx.x;
    const int warp = tid >> 5, lane = tid & 31;
    const int wm = (warp & 3) * 32;    // warp M offset
    const int wn = (warp >> 2) * 32;   // warp N offset
    const int grp = lane >> 2, tig = lane & 3;

    float acc[2][4][4];
    #pragma unroll
    for (int mt = 0; mt < 2; mt++)
        #pragma unroll
        for (int nt = 0; nt < 4; nt++)
            #pragma unroll
            for (int q = 0; q < 4; q++) acc[mt][nt][q] = 0.f;

    for (int k0 = 0; k0 < Kd; k0 += 32) {
        // stage A tile: 128x32 floats, 4 float4 per thread
        #pragma unroll
        for (int i = 0; i < 4; i++) {
            int idx = tid + i*256;
            int r = idx >> 3, c = (idx & 7) << 2;
            float4 v = *(const float4*)(A + (size_t)(m0 + r)*Kd + k0 + c);
            As[r][c+0] = f2tf32(v.x); As[r][c+1] = f2tf32(v.y);
            As[r][c+2] = f2tf32(v.z); As[r][c+3] = f2tf32(v.w);
        }
        // stage B tile: 64x32 floats, 2 float4 per thread (zero-pad n >= N)
        #pragma unroll
        for (int i = 0; i < 2; i++) {
            int idx = tid + i*256;
            int r = idx >> 3, c = (idx & 7) << 2;
            float4 v = make_float4(0.f, 0.f, 0.f, 0.f);
            if (n0 + r < N) v = *(const float4*)(W + (size_t)(n0 + r)*Kd + k0 + c);
            Bs[r][c+0] = f2tf32(v.x); Bs[r][c+1] = f2tf32(v.y);
            Bs[r][c+2] = f2tf32(v.z); Bs[r][c+3] = f2tf32(v.w);
        }
        __syncthreads();

        #pragma unroll
        for (int ks = 0; ks < 4; ks++) {
            int kc = ks * 8;
            unsigned af[2][4], bf[4][2];
            #pragma unroll
            for (int mt = 0; mt < 2; mt++) {
                int r = wm + mt*16 + grp;
                af[mt][0] = As[r    ][kc + tig];
                af[mt][1] = As[r + 8][kc + tig];
                af[mt][2] = As[r    ][kc + tig + 4];
                af[mt][3] = As[r + 8][kc + tig + 4];
            }
            #pragma unroll
            for (int nt = 0; nt < 4; nt++) {
                int r = wn + nt*8 + grp;
                bf[nt][0] = Bs[r][kc + tig];
                bf[nt][1] = Bs[r][kc + tig + 4];
            }
            #pragma unroll
            for (int mt = 0; mt < 2; mt++)
                #pragma unroll
                for (int nt = 0; nt < 4; nt++)
                    mma_tf32(acc[mt][nt], af[mt], bf[nt]);
        }
        __syncthreads();
    }

    // epilogue: c0,c1 -> row grp; c2,c3 -> row grp+8; cols 2*tig, 2*tig+1
    #pragma unroll
    for (int mt = 0; mt < 2; mt++) {
        #pragma unroll
        for (int nt = 0; nt < 4; nt++) {
            int m = m0 + wm + mt*16 + grp;
            int n = n0 + wn + nt*8 + 2*tig;
            if (n < N) {
                float2* p0 = (float2*)(Cout + (size_t)m*N + n);
                float2* p1 = (float2*)(Cout + (size_t)(m+8)*N + n);
                if (ACC) {
                    float2 v0 = *p0, v1 = *p1;
                    v0.x += acc[mt][nt][0]; v0.y += acc[mt][nt][1];
                    v1.x += acc[mt][nt][2]; v1.y += acc[mt][nt][3];
                    *p0 = v0; *p1 = v1;
                } else {
                    *p0 = make_float2(acc[mt][nt][0], acc[mt][nt][1]);
                    *p1 = make_float2(acc[mt][nt][2], acc[mt][nt][3]);
                }
            }
        }
    }
}

// ---------------- depthwise causal conv (K=4) + silu -------------------------
__global__ void k_conv(const float* __restrict__ w, const float* __restrict__ bias) {
    int idx = blockIdx.x * 256 + threadIdx.x;      // over Mtok*DIdim
    int d = idx & (DIdim - 1);
    int m = idx >> 9;
    int l = m & (Lseq - 1);
    float s = bias[d];
    const float* wd = w + d*4;
    #pragma unroll
    for (int k = 0; k < 4; k++) {
        int ls = l - 3 + k;
        if (ls >= 0) s += wd[k] * g_xz[(size_t)(m - 3 + k)*(2*DIdim) + d];
    }
    g_xc[idx] = siluf(s);
}

// ---------------- dt projection + softplus (K=16 tiny GEMM) ------------------
__global__ void k_dt(const float* __restrict__ dw, const float* __restrict__ db) {
    int m = blockIdx.x;
    int d = threadIdx.x;                 // 512 threads
    __shared__ float p[16];
    if (d < 16) p[d] = g_proj[(size_t)m*48 + d];
    __syncthreads();
    float s = db[d];
    #pragma unroll
    for (int r = 0; r < 16; r++) s += p[r] * dw[d*16 + r];
    g_dt[(size_t)m*DIdim + d] = (s > 20.f) ? s : log1pf(__expf(s));
}

// ---------------- selective scan --------------------------------------------
// block: 256 thr = 16 channels (dg) x 16 states (n). grid: Bsz * DIdim/16 = 256.
// dt/x/B/C staged through shared in 64-step double-buffered chunks.
__launch_bounds__(256)
__global__ void k_scan(const float* __restrict__ alog, const float* __restrict__ Dp) {
    __shared__ float s_dt[2][64][16];
    __shared__ float s_x [2][64][16];
    __shared__ float s_B [2][64][16];
    __shared__ float s_C [2][64][16];
    int b  = blockIdx.x >> 5;
    int d0 = (blockIdx.x & 31) << 4;
    int tid = threadIdx.x;
    int n  = tid & 15, dg = tid >> 4;
    int d  = d0 + dg;
    float Ad = -__expf(alog[d*DSdim + n]);
    float Dv = Dp[d];
    float h = 0.f;
    float rdt[4], rx[4], rB[4], rC[4];

    auto ldc = [&](int l0) {
        #pragma unroll
        for (int it = 0; it < 4; it++) {
            int i = tid + it*256;
            int l = i >> 4, j = i & 15;
            size_t t = (size_t)(b*Lseq + l0 + l);
            rdt[it] = g_dt[t*DIdim + d0 + j];
            rx[it]  = g_xc[t*DIdim + d0 + j];
            rB[it]  = g_proj[t*48 + 16 + j];
            rC[it]  = g_proj[t*48 + 32 + j];
        }
    };
    auto stc = [&](int buf) {
        #pragma unroll
        for (int it = 0; it < 4; it++) {
            int i = tid + it*256;
            int l = i >> 4, j = i & 15;
            s_dt[buf][l][j] = rdt[it]; s_x[buf][l][j] = rx[it];
            s_B [buf][l][j] = rB [it]; s_C[buf][l][j] = rC[it];
        }
    };

    ldc(0); stc(0); __syncthreads();
    for (int ch = 0; ch < 16; ch++) {
        int buf = ch & 1;
        if (ch < 15) ldc((ch + 1) * 64);    // prefetch next chunk into regs
        #pragma unroll 4
        for (int l = 0; l < 64; l++) {
            float dtv = s_dt[buf][l][dg];
            float xv  = s_x [buf][l][dg];
            float Bv  = s_B [buf][l][n];
            float Cv  = s_C [buf][l][n];
            h = h * __expf(dtv * Ad) + (dtv * xv) * Bv;
            float p = h * Cv;
            p += __shfl_xor_sync(0xffffffffu, p, 8, 16);
            p += __shfl_xor_sync(0xffffffffu, p, 4, 16);
            p += __shfl_xor_sync(0xffffffffu, p, 2, 16);
            p += __shfl_xor_sync(0xffffffffu, p, 1, 16);
            if (n == 0)
                g_y[(size_t)(b*Lseq + ch*64 + l)*DIdim + d] = p + xv * Dv;
        }
        __syncthreads();
        if (ch < 15) stc(buf ^ 1);
        __syncthreads();
    }
}

// ---------------- gate: y *= silu(z) -----------------------------------------
__global__ void k_gate() {
    int idx = blockIdx.x * 256 + threadIdx.x;   // Mtok*DIdim
    int m = idx >> 9, d = idx & 511;
    float z = g_xz[(size_t)m*(2*DIdim) + DIdim + d];
    g_y[idx] *= siluf(z);
}

// ---------------- SE: zero, pool, MLP ----------------------------------------
__global__ void k_zero_g0() {
    int i = blockIdx.x * 256 + threadIdx.x;
    if (i < Bsz*Cch) g_g0[i] = 0.f;
}
__global__ void k_pool() {
    int b = blockIdx.x >> 2, q = blockIdx.x & 3;
    int c = threadIdx.x;
    float s = 0.f;
    for (int l = q*256; l < q*256 + 256; l++)
        s += g_xs[(size_t)(b*Lseq + l)*Cch + c];
    atomicAdd(&g_g0[b*Cch + c], s * (1.f/1024.f));
}
__global__ void k_se(const float* __restrict__ w1, const float* __restrict__ b1,
                     const float* __restrict__ w2, const float* __restrict__ b2) {
    __shared__ float sg[Bsz*Cch];
    __shared__ float sh[Bsz*64];
    int t = threadIdx.x;
    for (int i = t; i < Bsz*Cch; i += 256) sg[i] = g_g0[i];
    __syncthreads();
    for (int i = t; i < Bsz*64; i += 256) {
        int b = i >> 6, j = i & 63;
        float s = b1[j];
        const float* wr = w1 + j*256;
        const float* gr = sg + b*256;
        #pragma unroll 8
        for (int c = 0; c < 256; c++) s += gr[c] * wr[c];
        sh[i] = fmaxf(s, 0.f);
    }
    __syncthreads();
    for (int i = t; i < Bsz*Cch; i += 256) {
        int b = i >> 8, c = i & 255;
        float s = b2[c];
        const float* wr = w2 + c*64;
        const float* hr = sh + b*64;
        #pragma unroll 8
        for (int j = 0; j < 64; j++) s += hr[j] * wr[j];
        g_gate[i] = 1.f / (1.f + __expf(-s));
    }
}

// ---------------- y = xo*g + residual, transposed to (b,c,l) -----------------
__global__ void k_ybn(const float* __restrict__ x) {
    __shared__ float tile[32][33];
    int b = blockIdx.z, c0 = blockIdx.y * 32, l0 = blockIdx.x * 32;
    int tx = threadIdx.x, ty = threadIdx.y;
    #pragma unroll
    for (int i = ty; i < 32; i += 8)
        tile[i][tx] = g_xs[(size_t)(b*Lseq + l0 + i)*Cch + c0 + tx];   // tile[l][c]
    __syncthreads();
    #pragma unroll
    for (int i = ty; i < 32; i += 8) {
        int c = c0 + i;
        size_t o = (size_t)(b*Cch + c)*Lseq + l0 + tx;
        g_ybn[o] = tile[tx][i] * g_gate[b*Cch + c] + x[o];
    }
}

// ---------------- batchnorm stats + apply ------------------------------------
__global__ void k_bnstats() {
    int c = blockIdx.x, t = threadIdx.x;
    float s = 0.f, s2 = 0.f;
    for (int b = 0; b < Bsz; b++)
        for (int l = t; l < Lseq; l += 256) {
            float v = g_ybn[(size_t)(b*Cch + c)*Lseq + l];
            s += v; s2 += v * v;
        }
    __shared__ float sh[256], sh2[256];
    sh[t] = s; sh2[t] = s2;
    __syncthreads();
    #pragma unroll
    for (int st = 128; st > 0; st >>= 1) {
        if (t < st) { sh[t] += sh[t + st]; sh2[t] += sh2[t + st]; }
        __syncthreads();
    }
    if (t == 0) {
        float mu  = sh[0] * (1.f/8192.f);
        float var = sh2[0] * (1.f/8192.f) - mu*mu;
        g_stats[c]       = mu;
        g_stats[Cch + c] = rsqrtf(var + 1e-5f);
    }
}
__global__ void k_bnapply(float* __restrict__ out, const float* __restrict__ bw,
                          const float* __restrict__ bb) {
    int idx = blockIdx.x * 256 + threadIdx.x;   // Bsz*Cch*Lseq
    int c = (idx >> 10) & 255;
    out[idx] = (g_ybn[idx] - g_stats[c]) * g_stats[Cch + c] * bw[c] + bb[c];
}

// ---------------- host driver ------------------------------------------------
extern "C" void kernel_launch(void* const* d_in, const int* in_sizes, int n_in,
                              void* d_out, int out_size)
{
    const float* x         = (const float*)d_in[0];
    const float* ln_w      = (const float*)d_in[1];
    const float* ln_b      = (const float*)d_in[2];
    const float* in_proj_w = (const float*)d_in[3];
    const float* conv_w    = (const float*)d_in[4];
    const float* conv_b    = (const float*)d_in[5];
    const float* x_proj_w  = (const float*)d_in[6];
    const float* dt_proj_w = (const float*)d_in[7];
    const float* dt_proj_b = (const float*)d_in[8];
    const float* A_log     = (const float*)d_in[9];
    const float* Dp        = (const float*)d_in[10];
    const float* out_proj_w= (const float*)d_in[11];
    const float* se_w1     = (const float*)d_in[12];
    const float* se_b1     = (const float*)d_in[13];
    const float* se_w2     = (const float*)d_in[14];
    const float* se_b2     = (const float*)d_in[15];
    const float* bn_w      = (const float*)d_in[16];
    const float* bn_b      = (const float*)d_in[17];
    float* out = (float*)d_out;

    void *p;
    cudaGetSymbolAddress(&p, g_xn);   float* pxn   = (float*)p;
    cudaGetSymbolAddress(&p, g_xz);   float* pxz   = (float*)p;
    cudaGetSymbolAddress(&p, g_xc);   float* pxc   = (float*)p;
    cudaGetSymbolAddress(&p, g_proj); float* pproj = (float*)p;
    cudaGetSymbolAddress(&p, g_y);    float* py    = (float*)p;
    cudaGetSymbolAddress(&p, g_xs);   float* pxs   = (float*)p;

    dim3 tb(32, 8);
    k_transpose_in<<<dim3(32, 8, Bsz), tb>>>(x);

    for (int i = 0; i < NLAYER; i++) {
        k_ln<<<Mtok, 256>>>(ln_w + i*Cch, ln_b + i*Cch);
        k_gemm_tc<false><<<dim3(16, 64), 256>>>(pxn, in_proj_w + (size_t)i*1024*256, pxz, 1024, 256);
        k_conv<<<Mtok*DIdim/256, 256>>>(conv_w + i*DIdim*4, conv_b + i*DIdim);
        k_gemm_tc<false><<<dim3(1, 64), 256>>>(pxc, x_proj_w + (size_t)i*48*512, pproj, 48, 512);
        k_dt<<<Mtok, 512>>>(dt_proj_w + i*DIdim*16, dt_proj_b + i*DIdim);
        k_scan<<<256, 256>>>(A_log + i*DIdim*DSdim, Dp + i*DIdim);
        k_gate<<<Mtok*DIdim/256, 256>>>();
        k_gemm_tc<true><<<dim3(4, 64), 256>>>(py, out_proj_w + (size_t)i*256*512, pxs, 256, 512);
    }

    k_zero_g0<<<8, 256>>>();
    k_pool<<<Bsz*4, 256>>>();
    k_se<<<1, 256>>>(se_w1, se_b1, se_w2, se_b2);
    k_ybn<<<dim3(32, 8, Bsz), tb>>>(x);
    k_bnstats<<<Cch, 256>>>();
    k_bnapply<<<Bsz*Cch*Lseq/256, 256>>>(out, bn_w, bn_b);

    (void)in_sizes; (void)n_in; (void)out_size;
}

// round 6
// speedup vs baseline: 1.8315x; 1.4343x over previous
#include <cuda_runtime.h>
#include <cuda_bf16.h>
#include <math.h>

#define Bsz   8
#define Cch   256
#define Lseq  1024
#define Mtok  8192      // Bsz*Lseq
#define DIdim 512
#define DSdim 16
#define NLAYER 4

// ---------------- scratch (device globals: no allocations allowed) ----------
// All vector-accessed buffers carry explicit alignment (uint4/float4/float2 casts).
__device__ __align__(128) float g_xs  [Mtok*Cch];          // running activations (b,l,c) fp32
__device__ __align__(128) __nv_bfloat16 g_xn_bf[Mtok*Cch]; // layernorm output (GEMM A)
__device__ __align__(128) float g_xz  [Mtok*2*DIdim];      // in_proj out: [:,0:512)=xin, [:,512:1024)=z
__device__ __align__(128) float g_xc  [Mtok*DIdim];        // conv+silu output fp32 (scan input)
__device__ __align__(128) __nv_bfloat16 g_xc_bf[Mtok*DIdim]; // conv+silu output bf16 (GEMM A)
__device__ __align__(128) float g_proj[Mtok*48];           // x_proj output (dtr|B|C) fp32
__device__ __align__(128) float g_dt  [Mtok*DIdim];        // softplus(dt) fp32
__device__ __align__(128) __nv_bfloat16 g_y_bf[Mtok*DIdim];// gated scan output bf16 (GEMM A)
__device__ __align__(128) float g_g0  [Bsz*Cch];           // SE pooled
__device__ __align__(128) float g_gate[Bsz*Cch];           // SE sigmoid gate
__device__ __align__(128) float g_ybn [Bsz*Cch*Lseq];      // pre-BN output (b,c,l)
__device__ __align__(128) float g_stats[2*Cch];            // BN mu, rstd
// bf16 weight copies
__device__ __align__(128) __nv_bfloat16 g_win_bf [NLAYER*2*DIdim*Cch];   // 4x1024x256
__device__ __align__(128) __nv_bfloat16 g_wx_bf  [NLAYER*48*DIdim];      // 4x48x512
__device__ __align__(128) __nv_bfloat16 g_wout_bf[NLAYER*Cch*DIdim];     // 4x256x512

// ---------------- helpers ----------------------------------------------------
__device__ __forceinline__ float siluf(float v) { return v / (1.f + __expf(-v)); }

// bf16 m16n8k16 row.col mma, fp32 accum
__device__ __forceinline__ void mma_bf16(float* d, const unsigned* a, const unsigned* b) {
    asm volatile(
        "mma.sync.aligned.m16n8k16.row.col.f32.bf16.bf16.f32 "
        "{%0,%1,%2,%3}, {%4,%5,%6,%7}, {%8,%9}, {%0,%1,%2,%3};"
        : "+f"(d[0]), "+f"(d[1]), "+f"(d[2]), "+f"(d[3])
        : "r"(a[0]), "r"(a[1]), "r"(a[2]), "r"(a[3]), "r"(b[0]), "r"(b[1]));
}

// ---------------- weight fp32 -> bf16 ---------------------------------------
__global__ void k_cvtw(const float* __restrict__ win, const float* __restrict__ wx,
                       const float* __restrict__ wo) {
    int i = blockIdx.x * 256 + threadIdx.x;
    if (i < NLAYER*2*DIdim*Cch) g_win_bf[i]  = __float2bfloat16(win[i]);
    if (i < NLAYER*48*DIdim)    g_wx_bf[i]   = __float2bfloat16(wx[i]);
    if (i < NLAYER*Cch*DIdim)   g_wout_bf[i] = __float2bfloat16(wo[i]);
}

// ---------------- input transpose (b,c,l) -> (b,l,c) -------------------------
__global__ void k_transpose_in(const float* __restrict__ x) {
    __shared__ float tile[32][33];
    int b = blockIdx.z, c0 = blockIdx.y * 32, l0 = blockIdx.x * 32;
    int tx = threadIdx.x, ty = threadIdx.y;
    #pragma unroll
    for (int i = ty; i < 32; i += 8)
        tile[i][tx] = x[(size_t)(b*Cch + c0 + i)*Lseq + l0 + tx];
    __syncthreads();
    #pragma unroll
    for (int i = ty; i < 32; i += 8)
        g_xs[(size_t)(b*Lseq + l0 + i)*Cch + c0 + tx] = tile[tx][i];
}

// ---------------- layernorm over C per token (warp-shuffle) ------------------
__global__ void k_ln(const float* __restrict__ w, const float* __restrict__ bias) {
    int m = blockIdx.x;
    int c = threadIdx.x;                     // 256 threads
    float v = g_xs[(size_t)m*Cch + c];
    float s = v, s2 = v * v;
    #pragma unroll
    for (int o = 16; o > 0; o >>= 1) {
        s  += __shfl_down_sync(0xffffffffu, s, o);
        s2 += __shfl_down_sync(0xffffffffu, s2, o);
    }
    __shared__ float ps[8], ps2[8];
    if ((c & 31) == 0) { ps[c >> 5] = s; ps2[c >> 5] = s2; }
    __syncthreads();
    float ts = 0.f, ts2 = 0.f;
    #pragma unroll
    for (int i = 0; i < 8; i++) { ts += ps[i]; ts2 += ps2[i]; }
    float mu  = ts * (1.f/256.f);
    float var = ts2 * (1.f/256.f) - mu*mu;
    g_xn_bf[(size_t)m*Cch + c] =
        __float2bfloat16((v - mu) * rsqrtf(var + 1e-5f) * w[c] + bias[c]);
}

// ---------------- bf16 tensor GEMM: C[M,N] (+)= A[M,K] @ W[N,K]^T ------------
// BM=128, BN=128, BK=32, 256 threads = 8 warps (4 along M x 2 along N),
// warp tile 32x64 = 2(mt) x 8(nt) m16n8k16 fragments.
// smem stored as u32 (bf16 pairs along k), row stride P=20 u32:
// fragment LDS addr = row*20 + tig(+4|+8|+12); {r*20 mod 32} = perfect 32-bank spread.
// M % 128 == 0, K % 32 == 0, N even (rows >= N zero-padded).
#define GP 20
template<bool ACC>
__launch_bounds__(256)
__global__ void k_gemm_bf(const __nv_bfloat16* __restrict__ A,
                          const __nv_bfloat16* __restrict__ W,
                          float* __restrict__ Cout, int N, int Kd)
{
    __shared__ __align__(16) unsigned As[128*GP];
    __shared__ __align__(16) unsigned Bs[128*GP];
    const int m0 = blockIdx.y * 128, n0 = blockIdx.x * 128;
    const int tid  = threadIdx.x;
    const int warp = tid >> 5, lane = tid & 31;
    const int wm = (warp & 3) * 32;    // warp M offset
    const int wn = (warp >> 2) * 64;   // warp N offset
    const int grp = lane >> 2, tig = lane & 3;

    float acc[2][8][4];
    #pragma unroll
    for (int mt = 0; mt < 2; mt++)
        #pragma unroll
        for (int nt = 0; nt < 8; nt++)
            #pragma unroll
            for (int q = 0; q < 4; q++) acc[mt][nt][q] = 0.f;

    for (int k0 = 0; k0 < Kd; k0 += 32) {
        // stage A: 128 rows x 32 bf16 = 512 uint4, 2 per thread
        #pragma unroll
        for (int i = 0; i < 2; i++) {
            int id = tid + i*256;
            int r = id >> 2, q4 = id & 3;          // q4*8 = k offset in bf16
            uint4 v = *(const uint4*)((const uint4*)(A + (size_t)(m0 + r)*Kd + k0) + q4);
            unsigned* p = &As[r*GP + q4*4];
            p[0] = v.x; p[1] = v.y; p[2] = v.z; p[3] = v.w;
        }
        // stage B: 128 rows (zero-pad rows >= N)
        #pragma unroll
        for (int i = 0; i < 2; i++) {
            int id = tid + i*256;
            int r = id >> 2, q4 = id & 3;
            uint4 v = make_uint4(0u, 0u, 0u, 0u);
            if (n0 + r < N)
                v = *(const uint4*)((const uint4*)(W + (size_t)(n0 + r)*Kd + k0) + q4);
            unsigned* p = &Bs[r*GP + q4*4];
            p[0] = v.x; p[1] = v.y; p[2] = v.z; p[3] = v.w;
        }
        __syncthreads();

        #pragma unroll
        for (int ks = 0; ks < 2; ks++) {           // two k16 steps
            int kc = ks * 8;                       // u32 offset
            unsigned af[2][4], bf[8][2];
            #pragma unroll
            for (int mt = 0; mt < 2; mt++) {
                int r = wm + mt*16 + grp;
                af[mt][0] = As[r*GP + kc + tig];
                af[mt][1] = As[(r+8)*GP + kc + tig];
                af[mt][2] = As[r*GP + kc + tig + 4];
                af[mt][3] = As[(r+8)*GP + kc + tig + 4];
            }
            #pragma unroll
            for (int nt = 0; nt < 8; nt++) {
                int r = wn + nt*8 + grp;
                bf[nt][0] = Bs[r*GP + kc + tig];
                bf[nt][1] = Bs[r*GP + kc + tig + 4];
            }
            #pragma unroll
            for (int mt = 0; mt < 2; mt++)
                #pragma unroll
                for (int nt = 0; nt < 8; nt++)
                    mma_bf16(acc[mt][nt], af[mt], bf[nt]);
        }
        __syncthreads();
    }

    // epilogue: c0,c1 -> (grp, 2tig); c2,c3 -> (grp+8, 2tig)
    #pragma unroll
    for (int mt = 0; mt < 2; mt++) {
        #pragma unroll
        for (int nt = 0; nt < 8; nt++) {
            int m = m0 + wm + mt*16 + grp;
            int n = n0 + wn + nt*8 + 2*tig;
            if (n < N) {
                float2* p0 = (float2*)(Cout + (size_t)m*N + n);
                float2* p1 = (float2*)(Cout + (size_t)(m+8)*N + n);
                if (ACC) {
                    float2 v0 = *p0, v1 = *p1;
                    v0.x += acc[mt][nt][0]; v0.y += acc[mt][nt][1];
                    v1.x += acc[mt][nt][2]; v1.y += acc[mt][nt][3];
                    *p0 = v0; *p1 = v1;
                } else {
                    *p0 = make_float2(acc[mt][nt][0], acc[mt][nt][1]);
                    *p1 = make_float2(acc[mt][nt][2], acc[mt][nt][3]);
                }
            }
        }
    }
}

// ---------------- depthwise causal conv (K=4) + silu -------------------------
__global__ void k_conv(const float* __restrict__ w, const float* __restrict__ bias) {
    int idx = blockIdx.x * 256 + threadIdx.x;      // over Mtok*DIdim
    int d = idx & (DIdim - 1);
    int m = idx >> 9;
    int l = m & (Lseq - 1);
    float s = bias[d];
    const float* wd = w + d*4;
    #pragma unroll
    for (int k = 0; k < 4; k++) {
        int ls = l - 3 + k;
        if (ls >= 0) s += wd[k] * g_xz[(size_t)(m - 3 + k)*(2*DIdim) + d];
    }
    float v = siluf(s);
    g_xc[idx] = v;
    g_xc_bf[idx] = __float2bfloat16(v);
}

// ---------------- dt projection + fast softplus ------------------------------
__global__ void k_dt(const float* __restrict__ dw, const float* __restrict__ db) {
    int m = blockIdx.x;
    int d = threadIdx.x;                 // 512 threads
    __shared__ float p[16];
    if (d < 16) p[d] = g_proj[(size_t)m*48 + d];
    __syncthreads();
    float s = db[d];
    const float4* w4 = (const float4*)(dw + d*16);
    #pragma unroll
    for (int r = 0; r < 4; r++) {
        float4 wv = w4[r];
        s += p[r*4+0]*wv.x + p[r*4+1]*wv.y + p[r*4+2]*wv.z + p[r*4+3]*wv.w;
    }
    g_dt[(size_t)m*DIdim + d] = (s > 15.f) ? s : __logf(1.f + __expf(s));
}

// ---------------- selective scan (deferred reduction, gate fused) ------------
// block: 256 thr = 16 channels (dg) x 16 states (n). grid: Bsz * DIdim/16 = 256.
// Serial phase per 32-step chunk: per-lane h recurrence only (no cross-lane dep);
// p = h*C goes to shared; reduction+D-term+silu(z) gate done vectorized after.
__launch_bounds__(256)
__global__ void k_scan2(const float* __restrict__ alog, const float* __restrict__ Dp) {
    __shared__ __align__(16) float s_dt[32][16], s_x[32][16], s_B[32][16], s_C[32][16];
    __shared__ __align__(16) float s_p[32][16][16];
    __shared__ float s_D[16];
    int b  = blockIdx.x >> 5;
    int d0 = (blockIdx.x & 31) << 4;
    int tid = threadIdx.x;
    int n  = tid & 15, dg = tid >> 4;
    int d  = d0 + dg;
    float Ad = -__expf(alog[d*DSdim + n]);
    if (tid < 16) s_D[tid] = Dp[d0 + tid];
    float h = 0.f;
    float rdt[2], rx[2], rB[2], rC[2];

    auto ldc = [&](int l0) {
        #pragma unroll
        for (int it = 0; it < 2; it++) {
            int i = tid + it*256;
            int l = i >> 4, j = i & 15;
            size_t t = (size_t)(b*Lseq + l0 + l);
            rdt[it] = g_dt[t*DIdim + d0 + j];
            rx[it]  = g_xc[t*DIdim + d0 + j];
            rB[it]  = g_proj[t*48 + 16 + j];
            rC[it]  = g_proj[t*48 + 32 + j];
        }
    };
    auto stc = [&]() {
        #pragma unroll
        for (int it = 0; it < 2; it++) {
            int i = tid + it*256;
            int l = i >> 4, j = i & 15;
            s_dt[l][j] = rdt[it]; s_x[l][j] = rx[it];
            s_B [l][j] = rB [it]; s_C[l][j] = rC[it];
        }
    };

    ldc(0); stc(); __syncthreads();
    for (int ch = 0; ch < 32; ch++) {
        int l0 = ch * 32;
        if (ch < 31) ldc(l0 + 32);      // LDGs in flight during serial phase
        #pragma unroll 8
        for (int l = 0; l < 32; l++) {
            float dtv = s_dt[l][dg];
            float w = __expf(dtv * Ad);
            float u = (dtv * s_x[l][dg]) * s_B[l][n];
            h = h * w + u;
            s_p[l][dg][n] = h * s_C[l][n];
        }
        __syncthreads();
        // reduce 16 states -> y, add D-term, gate with silu(z), write bf16
        #pragma unroll
        for (int it = 0; it < 2; it++) {
            int i = tid + it*256;
            int l = i >> 4, g = i & 15;
            float4 p0 = *(float4*)&s_p[l][g][0];
            float4 p1 = *(float4*)&s_p[l][g][4];
            float4 p2 = *(float4*)&s_p[l][g][8];
            float4 p3 = *(float4*)&s_p[l][g][12];
            float s = ((p0.x+p0.y)+(p0.z+p0.w)) + ((p1.x+p1.y)+(p1.z+p1.w))
                    + ((p2.x+p2.y)+(p2.z+p2.w)) + ((p3.x+p3.y)+(p3.z+p3.w));
            size_t t = (size_t)(b*Lseq + l0 + l);
            float yv = s + s_x[l][g] * s_D[g];
            float z = g_xz[t*(2*DIdim) + DIdim + d0 + g];
            yv *= z / (1.f + __expf(-z));
            g_y_bf[t*DIdim + d0 + g] = __float2bfloat16(yv);
        }
        __syncthreads();
        if (ch < 31) { stc(); __syncthreads(); }
    }
}

// ---------------- SE: zero, pool, MLP ----------------------------------------
__global__ void k_zero_g0() {
    int i = blockIdx.x * 256 + threadIdx.x;
    if (i < Bsz*Cch) g_g0[i] = 0.f;
}
__global__ void k_pool() {
    int b = blockIdx.x >> 2, q = blockIdx.x & 3;
    int c = threadIdx.x;
    float s = 0.f;
    for (int l = q*256; l < q*256 + 256; l++)
        s += g_xs[(size_t)(b*Lseq + l)*Cch + c];
    atomicAdd(&g_g0[b*Cch + c], s * (1.f/1024.f));
}
__global__ void k_se(const float* __restrict__ w1, const float* __restrict__ b1,
                     const float* __restrict__ w2, const float* __restrict__ b2) {
    __shared__ float sg[Bsz*Cch];
    __shared__ float sh[Bsz*64];
    int t = threadIdx.x;
    for (int i = t; i < Bsz*Cch; i += 256) sg[i] = g_g0[i];
    __syncthreads();
    for (int i = t; i < Bsz*64; i += 256) {
        int b = i >> 6, j = i & 63;
        float s = b1[j];
        const float* wr = w1 + j*256;
        const float* gr = sg + b*256;
        #pragma unroll 8
        for (int c = 0; c < 256; c++) s += gr[c] * wr[c];
        sh[i] = fmaxf(s, 0.f);
    }
    __syncthreads();
    for (int i = t; i < Bsz*Cch; i += 256) {
        int b = i >> 8, c = i & 255;
        float s = b2[c];
        const float* wr = w2 + c*64;
        const float* hr = sh + b*64;
        #pragma unroll 8
        for (int j = 0; j < 64; j++) s += hr[j] * wr[j];
        g_gate[i] = 1.f / (1.f + __expf(-s));
    }
}

// ---------------- y = xo*g + residual, transposed to (b,c,l) -----------------
__global__ void k_ybn(const float* __restrict__ x) {
    __shared__ float tile[32][33];
    int b = blockIdx.z, c0 = blockIdx.y * 32, l0 = blockIdx.x * 32;
    int tx = threadIdx.x, ty = threadIdx.y;
    #pragma unroll
    for (int i = ty; i < 32; i += 8)
        tile[i][tx] = g_xs[(size_t)(b*Lseq + l0 + i)*Cch + c0 + tx];   // tile[l][c]
    __syncthreads();
    #pragma unroll
    for (int i = ty; i < 32; i += 8) {
        int c = c0 + i;
        size_t o = (size_t)(b*Cch + c)*Lseq + l0 + tx;
        g_ybn[o] = tile[tx][i] * g_gate[b*Cch + c] + x[o];
    }
}

// ---------------- batchnorm stats + apply ------------------------------------
__global__ void k_bnstats() {
    int c = blockIdx.x, t = threadIdx.x;
    float s = 0.f, s2 = 0.f;
    for (int b = 0; b < Bsz; b++)
        for (int l = t; l < Lseq; l += 256) {
            float v = g_ybn[(size_t)(b*Cch + c)*Lseq + l];
            s += v; s2 += v * v;
        }
    __shared__ float sh[256], sh2[256];
    sh[t] = s; sh2[t] = s2;
    __syncthreads();
    #pragma unroll
    for (int st = 128; st > 0; st >>= 1) {
        if (t < st) { sh[t] += sh[t + st]; sh2[t] += sh2[t + st]; }
        __syncthreads();
    }
    if (t == 0) {
        float mu  = sh[0] * (1.f/8192.f);
        float var = sh2[0] * (1.f/8192.f) - mu*mu;
        g_stats[c]       = mu;
        g_stats[Cch + c] = rsqrtf(var + 1e-5f);
    }
}
__global__ void k_bnapply(float* __restrict__ out, const float* __restrict__ bw,
                          const float* __restrict__ bb) {
    int idx = blockIdx.x * 256 + threadIdx.x;   // Bsz*Cch*Lseq
    int c = (idx >> 10) & 255;
    out[idx] = (g_ybn[idx] - g_stats[c]) * g_stats[Cch + c] * bw[c] + bb[c];
}

// ---------------- host driver ------------------------------------------------
extern "C" void kernel_launch(void* const* d_in, const int* in_sizes, int n_in,
                              void* d_out, int out_size)
{
    const float* x         = (const float*)d_in[0];
    const float* ln_w      = (const float*)d_in[1];
    const float* ln_b      = (const float*)d_in[2];
    const float* in_proj_w = (const float*)d_in[3];
    const float* conv_w    = (const float*)d_in[4];
    const float* conv_b    = (const float*)d_in[5];
    const float* x_proj_w  = (const float*)d_in[6];
    const float* dt_proj_w = (const float*)d_in[7];
    const float* dt_proj_b = (const float*)d_in[8];
    const float* A_log     = (const float*)d_in[9];
    const float* Dp        = (const float*)d_in[10];
    const float* out_proj_w= (const float*)d_in[11];
    const float* se_w1     = (const float*)d_in[12];
    const float* se_b1     = (const float*)d_in[13];
    const float* se_w2     = (const float*)d_in[14];
    const float* se_b2     = (const float*)d_in[15];
    const float* bn_w      = (const float*)d_in[16];
    const float* bn_b      = (const float*)d_in[17];
    float* out = (float*)d_out;

    void *p;
    cudaGetSymbolAddress(&p, g_xn_bf);   __nv_bfloat16* pxn  = (__nv_bfloat16*)p;
    cudaGetSymbolAddress(&p, g_xz);      float* pxz  = (float*)p;
    cudaGetSymbolAddress(&p, g_xc_bf);   __nv_bfloat16* pxcb = (__nv_bfloat16*)p;
    cudaGetSymbolAddress(&p, g_proj);    float* pproj = (float*)p;
    cudaGetSymbolAddress(&p, g_y_bf);    __nv_bfloat16* pyb  = (__nv_bfloat16*)p;
    cudaGetSymbolAddress(&p, g_xs);      float* pxs  = (float*)p;
    cudaGetSymbolAddress(&p, g_win_bf);  __nv_bfloat16* pwin = (__nv_bfloat16*)p;
    cudaGetSymbolAddress(&p, g_wx_bf);   __nv_bfloat16* pwx  = (__nv_bfloat16*)p;
    cudaGetSymbolAddress(&p, g_wout_bf); __nv_bfloat16* pwo  = (__nv_bfloat16*)p;

    k_cvtw<<<(NLAYER*2*DIdim*Cch + 255)/256, 256>>>(in_proj_w, x_proj_w, out_proj_w);
    dim3 tb(32, 8);
    k_transpose_in<<<dim3(32, 8, Bsz), tb>>>(x);

    for (int i = 0; i < NLAYER; i++) {
        k_ln<<<Mtok, 256>>>(ln_w + i*Cch, ln_b + i*Cch);
        k_gemm_bf<false><<<dim3(8, 64), 256>>>(
            pxn, pwin + (size_t)i*2*DIdim*Cch, pxz, 2*DIdim, Cch);
        k_conv<<<Mtok*DIdim/256, 256>>>(conv_w + i*DIdim*4, conv_b + i*DIdim);
        k_gemm_bf<false><<<dim3(1, 64), 256>>>(
            pxcb, pwx + (size_t)i*48*DIdim, pproj, 48, DIdim);
        k_dt<<<Mtok, 512>>>(dt_proj_w + i*DIdim*16, dt_proj_b + i*DIdim);
        k_scan2<<<256, 256>>>(A_log + i*DIdim*DSdim, Dp + i*DIdim);
        k_gemm_bf<true><<<dim3(2, 64), 256>>>(
            pyb, pwo + (size_t)i*Cch*DIdim, pxs, Cch, DIdim);
    }

    k_zero_g0<<<8, 256>>>();
    k_pool<<<Bsz*4, 256>>>();
    k_se<<<1, 256>>>(se_w1, se_b1, se_w2, se_b2);
    k_ybn<<<dim3(32, 8, Bsz), tb>>>(x);
    k_bnstats<<<Cch, 256>>>();
    k_bnapply<<<Bsz*Cch*Lseq/256, 256>>>(out, bn_w, bn_b);

    (void)in_sizes; (void)n_in; (void)out_size;
}

// round 7
// speedup vs baseline: 2.1902x; 1.1959x over previous
#include <cuda_runtime.h>
#include <cuda_bf16.h>
#include <math.h>

#define Bsz   8
#define Cch   256
#define Lseq  1024
#define Mtok  8192      // Bsz*Lseq
#define DIdim 512
#define DSdim 16
#define NLAYER 4

// ---------------- scratch (device globals: no allocations allowed) ----------
__device__ __align__(128) float g_xs  [Mtok*Cch];            // residual stream (b,l,c) fp32
__device__ __align__(128) __nv_bfloat16 g_xn_bf[Mtok*Cch];   // layernorm out (GEMM A)
__device__ __align__(128) __nv_bfloat16 g_xz_bf[Mtok*2*DIdim]; // in_proj out bf16: xin | z
__device__ __align__(128) __nv_bfloat16 g_xc_bf[Mtok*DIdim]; // conv+silu out bf16
__device__ __align__(128) float g_proj[Mtok*48];             // x_proj out (dtr|B|C) fp32
__device__ __align__(128) __nv_bfloat16 g_y_bf[Mtok*DIdim];  // gated scan out bf16 (GEMM A)
__device__ __align__(128) float g_g0  [Bsz*Cch];             // SE pooled
__device__ __align__(128) float g_gate[Bsz*Cch];             // SE sigmoid gate
__device__ __align__(128) float g_ybn [Bsz*Cch*Lseq];        // pre-BN output (b,c,l)
__device__ __align__(128) float g_stats[2*Cch];              // BN mu, rstd
// bf16 weight copies
__device__ __align__(128) __nv_bfloat16 g_win_bf [NLAYER*2*DIdim*Cch];
__device__ __align__(128) __nv_bfloat16 g_wx_bf  [NLAYER*48*DIdim];
__device__ __align__(128) __nv_bfloat16 g_wout_bf[NLAYER*Cch*DIdim];

// ---------------- helpers ----------------------------------------------------
__device__ __forceinline__ float siluf(float v) { return v / (1.f + __expf(-v)); }

__device__ __forceinline__ void mma_bf16(float* d, const unsigned* a, const unsigned* b) {
    asm volatile(
        "mma.sync.aligned.m16n8k16.row.col.f32.bf16.bf16.f32 "
        "{%0,%1,%2,%3}, {%4,%5,%6,%7}, {%8,%9}, {%0,%1,%2,%3};"
        : "+f"(d[0]), "+f"(d[1]), "+f"(d[2]), "+f"(d[3])
        : "r"(a[0]), "r"(a[1]), "r"(a[2]), "r"(a[3]), "r"(b[0]), "r"(b[1]));
}

__device__ __forceinline__ unsigned smaddr(const void* p) {
    return (unsigned)__cvta_generic_to_shared(p);
}
__device__ __forceinline__ void cpasync16(unsigned dst, const void* src, int srcbytes) {
    asm volatile("cp.async.cg.shared.global [%0], [%1], 16, %2;"
                 :: "r"(dst), "l"(src), "r"(srcbytes));
}

// ---------------- weight fp32 -> bf16 ---------------------------------------
__global__ void k_cvtw(const float* __restrict__ win, const float* __restrict__ wx,
                       const float* __restrict__ wo) {
    int i = blockIdx.x * 256 + threadIdx.x;
    if (i < NLAYER*2*DIdim*Cch) g_win_bf[i]  = __float2bfloat16(win[i]);
    if (i < NLAYER*48*DIdim)    g_wx_bf[i]   = __float2bfloat16(wx[i]);
    if (i < NLAYER*Cch*DIdim)   g_wout_bf[i] = __float2bfloat16(wo[i]);
}

// ---------------- input transpose (b,c,l) -> (b,l,c) -------------------------
__global__ void k_transpose_in(const float* __restrict__ x) {
    __shared__ float tile[32][33];
    int b = blockIdx.z, c0 = blockIdx.y * 32, l0 = blockIdx.x * 32;
    int tx = threadIdx.x, ty = threadIdx.y;
    #pragma unroll
    for (int i = ty; i < 32; i += 8)
        tile[i][tx] = x[(size_t)(b*Cch + c0 + i)*Lseq + l0 + tx];
    __syncthreads();
    #pragma unroll
    for (int i = ty; i < 32; i += 8)
        g_xs[(size_t)(b*Lseq + l0 + i)*Cch + c0 + tx] = tile[tx][i];
}

// ---------------- layernorm over C per token (warp-shuffle) ------------------
__global__ void k_ln(const float* __restrict__ w, const float* __restrict__ bias) {
    int m = blockIdx.x;
    int c = threadIdx.x;                     // 256 threads
    float v = g_xs[(size_t)m*Cch + c];
    float s = v, s2 = v * v;
    #pragma unroll
    for (int o = 16; o > 0; o >>= 1) {
        s  += __shfl_down_sync(0xffffffffu, s, o);
        s2 += __shfl_down_sync(0xffffffffu, s2, o);
    }
    __shared__ float ps[8], ps2[8];
    if ((c & 31) == 0) { ps[c >> 5] = s; ps2[c >> 5] = s2; }
    __syncthreads();
    float ts = 0.f, ts2 = 0.f;
    #pragma unroll
    for (int i = 0; i < 8; i++) { ts += ps[i]; ts2 += ps2[i]; }
    float mu  = ts * (1.f/256.f);
    float var = ts2 * (1.f/256.f) - mu*mu;
    g_xn_bf[(size_t)m*Cch + c] =
        __float2bfloat16((v - mu) * rsqrtf(var + 1e-5f) * w[c] + bias[c]);
}

// ---------------- bf16 tensor GEMM: C[M,N] (+)= A[M,K] @ W[N,K]^T ------------
// BM=128, BN=128, BK=32, 256 threads = 8 warps (4 M x 2 N), warp tile 32x64.
// cp.async double-buffered staging; smem pad stride GP=20 u32 (bank-clean frags).
// BF16OUT: write __nv_bfloat162 pairs instead of float2 (no ACC support needed).
#define GP 20
template<bool ACC, bool BF16OUT>
__launch_bounds__(256)
__global__ void k_gemm_bf(const __nv_bfloat16* __restrict__ A,
                          const __nv_bfloat16* __restrict__ W,
                          void* __restrict__ CoutV, int N, int Kd)
{
    __shared__ __align__(16) unsigned As[2][128*GP];
    __shared__ __align__(16) unsigned Bs[2][128*GP];
    const int m0 = blockIdx.y * 128, n0 = blockIdx.x * 128;
    const int tid  = threadIdx.x;
    const int warp = tid >> 5, lane = tid & 31;
    const int wm = (warp & 3) * 32;
    const int wn = (warp >> 2) * 64;
    const int grp = lane >> 2, tig = lane & 3;

    float acc[2][8][4];
    #pragma unroll
    for (int mt = 0; mt < 2; mt++)
        #pragma unroll
        for (int nt = 0; nt < 8; nt++)
            #pragma unroll
            for (int q = 0; q < 4; q++) acc[mt][nt][q] = 0.f;

    const int NC = Kd >> 5;

    auto preload = [&](int c) {
        int buf = c & 1;
        #pragma unroll
        for (int i = 0; i < 2; i++) {
            int id = tid + i*256;
            int rr = id >> 2, qq = id & 3;
            cpasync16(smaddr(&As[buf][rr*GP + qq*4]),
                      A + (size_t)(m0 + rr)*Kd + c*32 + qq*8, 16);
        }
        #pragma unroll
        for (int i = 0; i < 2; i++) {
            int id = tid + i*256;
            int rr = id >> 2, qq = id & 3;
            int valid = (n0 + rr < N);
            cpasync16(smaddr(&Bs[buf][rr*GP + qq*4]),
                      W + (size_t)(valid ? (n0 + rr) : 0)*Kd + c*32 + qq*8,
                      valid ? 16 : 0);
        }
        asm volatile("cp.async.commit_group;");
    };

    preload(0);
    for (int c = 0; c < NC; c++) {
        if (c + 1 < NC) {
            preload(c + 1);
            asm volatile("cp.async.wait_group 1;");
        } else {
            asm volatile("cp.async.wait_group 0;");
        }
        __syncthreads();
        const unsigned* Ab = As[c & 1];
        const unsigned* Bb = Bs[c & 1];
        #pragma unroll
        for (int ks = 0; ks < 2; ks++) {
            int kc = ks * 8;
            unsigned af[2][4], bf[8][2];
            #pragma unroll
            for (int mt = 0; mt < 2; mt++) {
                int r = wm + mt*16 + grp;
                af[mt][0] = Ab[r*GP + kc + tig];
                af[mt][1] = Ab[(r+8)*GP + kc + tig];
                af[mt][2] = Ab[r*GP + kc + tig + 4];
                af[mt][3] = Ab[(r+8)*GP + kc + tig + 4];
            }
            #pragma unroll
            for (int nt = 0; nt < 8; nt++) {
                int r = wn + nt*8 + grp;
                bf[nt][0] = Bb[r*GP + kc + tig];
                bf[nt][1] = Bb[r*GP + kc + tig + 4];
            }
            #pragma unroll
            for (int mt = 0; mt < 2; mt++)
                #pragma unroll
                for (int nt = 0; nt < 8; nt++)
                    mma_bf16(acc[mt][nt], af[mt], bf[nt]);
        }
        __syncthreads();
    }

    // epilogue: c0,c1 -> (grp, 2tig); c2,c3 -> (grp+8, 2tig)
    #pragma unroll
    for (int mt = 0; mt < 2; mt++) {
        #pragma unroll
        for (int nt = 0; nt < 8; nt++) {
            int m = m0 + wm + mt*16 + grp;
            int n = n0 + wn + nt*8 + 2*tig;
            if (n < N) {
                if (BF16OUT) {
                    __nv_bfloat16* Cb = (__nv_bfloat16*)CoutV;
                    *(__nv_bfloat162*)(Cb + (size_t)m*N + n) =
                        __floats2bfloat162_rn(acc[mt][nt][0], acc[mt][nt][1]);
                    *(__nv_bfloat162*)(Cb + (size_t)(m+8)*N + n) =
                        __floats2bfloat162_rn(acc[mt][nt][2], acc[mt][nt][3]);
                } else {
                    float* Cf = (float*)CoutV;
                    float2* p0 = (float2*)(Cf + (size_t)m*N + n);
                    float2* p1 = (float2*)(Cf + (size_t)(m+8)*N + n);
                    if (ACC) {
                        float2 v0 = *p0, v1 = *p1;
                        v0.x += acc[mt][nt][0]; v0.y += acc[mt][nt][1];
                        v1.x += acc[mt][nt][2]; v1.y += acc[mt][nt][3];
                        *p0 = v0; *p1 = v1;
                    } else {
                        *p0 = make_float2(acc[mt][nt][0], acc[mt][nt][1]);
                        *p1 = make_float2(acc[mt][nt][2], acc[mt][nt][3]);
                    }
                }
            }
        }
    }
}

// ---------------- depthwise causal conv (K=4) + silu (bf16 in/out) -----------
__global__ void k_conv(const float* __restrict__ w, const float* __restrict__ bias) {
    int idx = blockIdx.x * 256 + threadIdx.x;      // over Mtok*DIdim
    int d = idx & (DIdim - 1);
    int m = idx >> 9;
    int l = m & (Lseq - 1);
    float s = bias[d];
    const float* wd = w + d*4;
    #pragma unroll
    for (int k = 0; k < 4; k++) {
        int ls = l - 3 + k;
        if (ls >= 0)
            s += wd[k] * __bfloat162float(g_xz_bf[(size_t)(m - 3 + k)*(2*DIdim) + d]);
    }
    g_xc_bf[idx] = __float2bfloat16(siluf(s));
}

// ---------------- selective scan (dt fused, deferred reduction, gated) -------
// block: 256 thr = 16 channels (dg) x 16 states (n). grid: Bsz * DIdim/16 = 256.
// Per 32-token chunk: stage proj/x/B/C -> compute dt in-block (16x16 dot vs
// smem dw tile) -> serial h recurrence (no cross-lane dep) -> vectorized
// 16-state reduction + D-term + silu(z) gate -> bf16 store.
__launch_bounds__(256)
__global__ void k_scan2(const float* __restrict__ alog, const float* __restrict__ Dp,
                        const float* __restrict__ dw, const float* __restrict__ db) {
    __shared__ __align__(16) float s_dt[32][16], s_x[32][16], s_B[32][16], s_C[32][16];
    __shared__ __align__(16) float s_P[32][16];
    __shared__ __align__(16) float s_p[32][16][16];
    __shared__ float s_dw[16][17];
    __shared__ float s_db[16], s_D[16];
    int b  = blockIdx.x >> 5;
    int d0 = (blockIdx.x & 31) << 4;
    int tid = threadIdx.x;
    int n  = tid & 15, dg = tid >> 4;
    int d  = d0 + dg;
    float Ad = -__expf(alog[d*DSdim + n]);
    if (tid < 16) { s_D[tid] = Dp[d0 + tid]; s_db[tid] = db[d0 + tid]; }
    s_dw[tid >> 4][tid & 15] = dw[(d0 + (tid >> 4))*16 + (tid & 15)];
    float h = 0.f;
    float rP[2], rx[2], rB[2], rC[2];

    auto ldc = [&](int l0) {
        #pragma unroll
        for (int it = 0; it < 2; it++) {
            int i = tid + it*256;
            int l = i >> 4, j = i & 15;
            size_t t = (size_t)(b*Lseq + l0 + l);
            rP[it] = g_proj[t*48 + j];
            rx[it] = __bfloat162float(g_xc_bf[t*DIdim + d0 + j]);
            rB[it] = g_proj[t*48 + 16 + j];
            rC[it] = g_proj[t*48 + 32 + j];
        }
    };
    auto stc = [&]() {
        #pragma unroll
        for (int it = 0; it < 2; it++) {
            int i = tid + it*256;
            int l = i >> 4, j = i & 15;
            s_P[l][j] = rP[it]; s_x[l][j] = rx[it];
            s_B[l][j] = rB[it]; s_C[l][j] = rC[it];
        }
    };
    auto dtcalc = [&]() {
        #pragma unroll
        for (int it = 0; it < 2; it++) {
            int i = tid + it*256;
            int l = i >> 4, j = i & 15;
            float s = s_db[j];
            #pragma unroll
            for (int r = 0; r < 16; r++) s += s_P[l][r] * s_dw[j][r];
            s_dt[l][j] = (s > 15.f) ? s : __logf(1.f + __expf(s));
        }
    };

    ldc(0); stc(); __syncthreads(); dtcalc(); __syncthreads();
    for (int ch = 0; ch < 32; ch++) {
        int l0 = ch * 32;
        if (ch < 31) ldc(l0 + 32);      // LDGs in flight during serial phase
        #pragma unroll 8
        for (int l = 0; l < 32; l++) {
            float dtv = s_dt[l][dg];
            float w = __expf(dtv * Ad);
            float u = (dtv * s_x[l][dg]) * s_B[l][n];
            h = h * w + u;
            s_p[l][dg][n] = h * s_C[l][n];
        }
        __syncthreads();
        // reduce 16 states -> y, add D-term, gate with silu(z), write bf16
        #pragma unroll
        for (int it = 0; it < 2; it++) {
            int i = tid + it*256;
            int l = i >> 4, g = i & 15;
            float4 p0 = *(float4*)&s_p[l][g][0];
            float4 p1 = *(float4*)&s_p[l][g][4];
            float4 p2 = *(float4*)&s_p[l][g][8];
            float4 p3 = *(float4*)&s_p[l][g][12];
            float s = ((p0.x+p0.y)+(p0.z+p0.w)) + ((p1.x+p1.y)+(p1.z+p1.w))
                    + ((p2.x+p2.y)+(p2.z+p2.w)) + ((p3.x+p3.y)+(p3.z+p3.w));
            size_t t = (size_t)(b*Lseq + l0 + l);
            float yv = s + s_x[l][g] * s_D[g];
            float z = __bfloat162float(g_xz_bf[t*(2*DIdim) + DIdim + d0 + g]);
            yv *= z / (1.f + __expf(-z));
            g_y_bf[t*DIdim + d0 + g] = __float2bfloat16(yv);
        }
        __syncthreads();
        if (ch < 31) { stc(); __syncthreads(); dtcalc(); __syncthreads(); }
    }
}

// ---------------- SE: zero, pool, MLP ----------------------------------------
__global__ void k_zero_g0() {
    int i = blockIdx.x * 256 + threadIdx.x;
    if (i < Bsz*Cch) g_g0[i] = 0.f;
}
__global__ void k_pool() {
    int b = blockIdx.x >> 2, q = blockIdx.x & 3;
    int c = threadIdx.x;
    float s = 0.f;
    for (int l = q*256; l < q*256 + 256; l++)
        s += g_xs[(size_t)(b*Lseq + l)*Cch + c];
    atomicAdd(&g_g0[b*Cch + c], s * (1.f/1024.f));
}
__global__ void k_se(const float* __restrict__ w1, const float* __restrict__ b1,
                     const float* __restrict__ w2, const float* __restrict__ b2) {
    __shared__ float sg[Bsz*Cch];
    __shared__ float sh[Bsz*64];
    int t = threadIdx.x;
    for (int i = t; i < Bsz*Cch; i += 256) sg[i] = g_g0[i];
    __syncthreads();
    for (int i = t; i < Bsz*64; i += 256) {
        int b = i >> 6, j = i & 63;
        float s = b1[j];
        const float* wr = w1 + j*256;
        const float* gr = sg + b*256;
        #pragma unroll 8
        for (int c = 0; c < 256; c++) s += gr[c] * wr[c];
        sh[i] = fmaxf(s, 0.f);
    }
    __syncthreads();
    for (int i = t; i < Bsz*Cch; i += 256) {
        int b = i >> 8, c = i & 255;
        float s = b2[c];
        const float* wr = w2 + c*64;
        const float* hr = sh + b*64;
        #pragma unroll 8
        for (int j = 0; j < 64; j++) s += hr[j] * wr[j];
        g_gate[i] = 1.f / (1.f + __expf(-s));
    }
}

// ---------------- y = xo*g + residual, transposed to (b,c,l) -----------------
__global__ void k_ybn(const float* __restrict__ x) {
    __shared__ float tile[32][33];
    int b = blockIdx.z, c0 = blockIdx.y * 32, l0 = blockIdx.x * 32;
    int tx = threadIdx.x, ty = threadIdx.y;
    #pragma unroll
    for (int i = ty; i < 32; i += 8)
        tile[i][tx] = g_xs[(size_t)(b*Lseq + l0 + i)*Cch + c0 + tx];   // tile[l][c]
    __syncthreads();
    #pragma unroll
    for (int i = ty; i < 32; i += 8) {
        int c = c0 + i;
        size_t o = (size_t)(b*Cch + c)*Lseq + l0 + tx;
        g_ybn[o] = tile[tx][i] * g_gate[b*Cch + c] + x[o];
    }
}

// ---------------- batchnorm stats + apply ------------------------------------
__global__ void k_bnstats() {
    int c = blockIdx.x, t = threadIdx.x;
    float s = 0.f, s2 = 0.f;
    for (int b = 0; b < Bsz; b++)
        for (int l = t; l < Lseq; l += 256) {
            float v = g_ybn[(size_t)(b*Cch + c)*Lseq + l];
            s += v; s2 += v * v;
        }
    __shared__ float sh[256], sh2[256];
    sh[t] = s; sh2[t] = s2;
    __syncthreads();
    #pragma unroll
    for (int st = 128; st > 0; st >>= 1) {
        if (t < st) { sh[t] += sh[t + st]; sh2[t] += sh2[t + st]; }
        __syncthreads();
    }
    if (t == 0) {
        float mu  = sh[0] * (1.f/8192.f);
        float var = sh2[0] * (1.f/8192.f) - mu*mu;
        g_stats[c]       = mu;
        g_stats[Cch + c] = rsqrtf(var + 1e-5f);
    }
}
__global__ void k_bnapply(float* __restrict__ out, const float* __restrict__ bw,
                          const float* __restrict__ bb) {
    int idx = blockIdx.x * 256 + threadIdx.x;   // Bsz*Cch*Lseq
    int c = (idx >> 10) & 255;
    out[idx] = (g_ybn[idx] - g_stats[c]) * g_stats[Cch + c] * bw[c] + bb[c];
}

// ---------------- host driver ------------------------------------------------
extern "C" void kernel_launch(void* const* d_in, const int* in_sizes, int n_in,
                              void* d_out, int out_size)
{
    const float* x         = (const float*)d_in[0];
    const float* ln_w      = (const float*)d_in[1];
    const float* ln_b      = (const float*)d_in[2];
    const float* in_proj_w = (const float*)d_in[3];
    const float* conv_w    = (const float*)d_in[4];
    const float* conv_b    = (const float*)d_in[5];
    const float* x_proj_w  = (const float*)d_in[6];
    const float* dt_proj_w = (const float*)d_in[7];
    const float* dt_proj_b = (const float*)d_in[8];
    const float* A_log     = (const float*)d_in[9];
    const float* Dp        = (const float*)d_in[10];
    const float* out_proj_w= (const float*)d_in[11];
    const float* se_w1     = (const float*)d_in[12];
    const float* se_b1     = (const float*)d_in[13];
    const float* se_w2     = (const float*)d_in[14];
    const float* se_b2     = (const float*)d_in[15];
    const float* bn_w      = (const float*)d_in[16];
    const float* bn_b      = (const float*)d_in[17];
    float* out = (float*)d_out;

    void *p;
    cudaGetSymbolAddress(&p, g_xn_bf);   __nv_bfloat16* pxn  = (__nv_bfloat16*)p;
    cudaGetSymbolAddress(&p, g_xz_bf);   __nv_bfloat16* pxzb = (__nv_bfloat16*)p;
    cudaGetSymbolAddress(&p, g_xc_bf);   __nv_bfloat16* pxcb = (__nv_bfloat16*)p;
    cudaGetSymbolAddress(&p, g_proj);    float* pproj = (float*)p;
    cudaGetSymbolAddress(&p, g_y_bf);    __nv_bfloat16* pyb  = (__nv_bfloat16*)p;
    cudaGetSymbolAddress(&p, g_xs);      float* pxs  = (float*)p;
    cudaGetSymbolAddress(&p, g_win_bf);  __nv_bfloat16* pwin = (__nv_bfloat16*)p;
    cudaGetSymbolAddress(&p, g_wx_bf);   __nv_bfloat16* pwx  = (__nv_bfloat16*)p;
    cudaGetSymbolAddress(&p, g_wout_bf); __nv_bfloat16* pwo  = (__nv_bfloat16*)p;

    k_cvtw<<<(NLAYER*2*DIdim*Cch + 255)/256, 256>>>(in_proj_w, x_proj_w, out_proj_w);
    dim3 tb(32, 8);
    k_transpose_in<<<dim3(32, 8, Bsz), tb>>>(x);

    for (int i = 0; i < NLAYER; i++) {
        k_ln<<<Mtok, 256>>>(ln_w + i*Cch, ln_b + i*Cch);
        k_gemm_bf<false, true><<<dim3(8, 64), 256>>>(
            pxn, pwin + (size_t)i*2*DIdim*Cch, pxzb, 2*DIdim, Cch);
        k_conv<<<Mtok*DIdim/256, 256>>>(conv_w + i*DIdim*4, conv_b + i*DIdim);
        k_gemm_bf<false, false><<<dim3(1, 64), 256>>>(
            pxcb, pwx + (size_t)i*48*DIdim, pproj, 48, DIdim);
        k_scan2<<<256, 256>>>(A_log + i*DIdim*DSdim, Dp + i*DIdim,
                              dt_proj_w + i*DIdim*16, dt_proj_b + i*DIdim);
        k_gemm_bf<true, false><<<dim3(2, 64), 256>>>(
            pyb, pwo + (size_t)i*Cch*DIdim, pxs, Cch, DIdim);
    }

    k_zero_g0<<<8, 256>>>();
    k_pool<<<Bsz*4, 256>>>();
    k_se<<<1, 256>>>(se_w1, se_b1, se_w2, se_b2);
    k_ybn<<<dim3(32, 8, Bsz), tb>>>(x);
    k_bnstats<<<Cch, 256>>>();
    k_bnapply<<<Bsz*Cch*Lseq/256, 256>>>(out, bn_w, bn_b);

    (void)in_sizes; (void)n_in; (void)out_size;
}

// round 8
// speedup vs baseline: 2.3002x; 1.0502x over previous
#include <cuda_runtime.h>
#include <cuda_bf16.h>
#include <math.h>

#define Bsz   8
#define Cch   256
#define Lseq  1024
#define Mtok  8192      // Bsz*Lseq
#define DIdim 512
#define DSdim 16
#define NLAYER 4

// ---------------- scratch (device globals: no allocations allowed) ----------
__device__ __align__(128) float g_xs  [Mtok*Cch];            // residual stream (b,l,c) fp32
__device__ __align__(128) __nv_bfloat16 g_xn_bf[Mtok*Cch];   // layernorm out (GEMM A)
__device__ __align__(128) __nv_bfloat16 g_xz_bf[Mtok*2*DIdim]; // in_proj out bf16: xin | z
__device__ __align__(128) __nv_bfloat16 g_xc_bf[Mtok*DIdim]; // conv+silu out bf16
__device__ __align__(128) float g_proj[Mtok*48];             // x_proj out (dtr|B|C) fp32
__device__ __align__(128) __nv_bfloat16 g_y_bf[Mtok*DIdim];  // gated scan out bf16 (GEMM A)
__device__ __align__(128) float g_g0  [Bsz*Cch];             // SE pooled
__device__ __align__(128) float g_gate[Bsz*Cch];             // SE sigmoid gate
__device__ __align__(128) float g_ybn [Bsz*Cch*Lseq];        // pre-BN output (b,c,l)
__device__ __align__(128) float g_stats[2*Cch];              // BN mu, rstd
// bf16 weight copies
__device__ __align__(128) __nv_bfloat16 g_win_bf [NLAYER*2*DIdim*Cch];
__device__ __align__(128) __nv_bfloat16 g_wx_bf  [NLAYER*48*DIdim];
__device__ __align__(128) __nv_bfloat16 g_wout_bf[NLAYER*Cch*DIdim];

// ---------------- helpers ----------------------------------------------------
__device__ __forceinline__ float siluf(float v) { return v / (1.f + __expf(-v)); }

__device__ __forceinline__ void mma_bf16(float* d, const unsigned* a, const unsigned* b) {
    asm volatile(
        "mma.sync.aligned.m16n8k16.row.col.f32.bf16.bf16.f32 "
        "{%0,%1,%2,%3}, {%4,%5,%6,%7}, {%8,%9}, {%0,%1,%2,%3};"
        : "+f"(d[0]), "+f"(d[1]), "+f"(d[2]), "+f"(d[3])
        : "r"(a[0]), "r"(a[1]), "r"(a[2]), "r"(a[3]), "r"(b[0]), "r"(b[1]));
}
__device__ __forceinline__ void ldsm4(unsigned& r0, unsigned& r1, unsigned& r2,
                                      unsigned& r3, unsigned addr) {
    asm volatile("ldmatrix.sync.aligned.m8n8.x4.shared.b16 {%0,%1,%2,%3}, [%4];"
                 : "=r"(r0), "=r"(r1), "=r"(r2), "=r"(r3) : "r"(addr));
}
__device__ __forceinline__ unsigned smaddr(const void* p) {
    return (unsigned)__cvta_generic_to_shared(p);
}
__device__ __forceinline__ void cpasync16(unsigned dst, const void* src, int srcbytes) {
    asm volatile("cp.async.cg.shared.global [%0], [%1], 16, %2;"
                 :: "r"(dst), "l"(src), "r"(srcbytes));
}

// ---------------- weight fp32 -> bf16 ---------------------------------------
__global__ void k_cvtw(const float* __restrict__ win, const float* __restrict__ wx,
                       const float* __restrict__ wo) {
    int i = blockIdx.x * 256 + threadIdx.x;
    if (i < NLAYER*2*DIdim*Cch) g_win_bf[i]  = __float2bfloat16(win[i]);
    if (i < NLAYER*48*DIdim)    g_wx_bf[i]   = __float2bfloat16(wx[i]);
    if (i < NLAYER*Cch*DIdim)   g_wout_bf[i] = __float2bfloat16(wo[i]);
}

// ---------------- input transpose (b,c,l) -> (b,l,c) -------------------------
__global__ void k_transpose_in(const float* __restrict__ x) {
    __shared__ float tile[32][33];
    int b = blockIdx.z, c0 = blockIdx.y * 32, l0 = blockIdx.x * 32;
    int tx = threadIdx.x, ty = threadIdx.y;
    #pragma unroll
    for (int i = ty; i < 32; i += 8)
        tile[i][tx] = x[(size_t)(b*Cch + c0 + i)*Lseq + l0 + tx];
    __syncthreads();
    #pragma unroll
    for (int i = ty; i < 32; i += 8)
        g_xs[(size_t)(b*Lseq + l0 + i)*Cch + c0 + tx] = tile[tx][i];
}

// ---------------- layernorm: warp per token, 8 tokens/block ------------------
__global__ void k_ln(const float* __restrict__ w, const float* __restrict__ bias) {
    int warp = threadIdx.x >> 5, lane = threadIdx.x & 31;
    int m = blockIdx.x * 8 + warp;
    const float* row = g_xs + (size_t)m*Cch;
    float v[8], s = 0.f, s2 = 0.f;
    #pragma unroll
    for (int j = 0; j < 8; j++) {
        v[j] = row[lane + 32*j];
        s += v[j]; s2 += v[j]*v[j];
    }
    #pragma unroll
    for (int o = 16; o > 0; o >>= 1) {
        s  += __shfl_xor_sync(0xffffffffu, s, o);
        s2 += __shfl_xor_sync(0xffffffffu, s2, o);
    }
    float mu = s * (1.f/256.f);
    float r  = rsqrtf(s2 * (1.f/256.f) - mu*mu + 1e-5f);
    #pragma unroll
    for (int j = 0; j < 8; j++) {
        int c = lane + 32*j;
        g_xn_bf[(size_t)m*Cch + c] = __float2bfloat16((v[j] - mu)*r*w[c] + bias[c]);
    }
}

// ---------------- bf16 tensor GEMM: C[M,N] (+)= A[M,K] @ W[N,K]^T ------------
// BM=128, BN=128, BK=32, 256 threads = 8 warps (4 M x 2 N), warp tile 32x64.
// 3-stage cp.async pipeline; ldmatrix.x4 fragment loads; GP=20 pad keeps both
// LDSM phases and staging conflict-free. Dynamic smem (61.4 KB).
#define GP 20
#define STG 3
#define TILEU (128*GP)
#define GEMM_SMEM (2*STG*TILEU*4)
template<bool ACC, bool BF16OUT>
__launch_bounds__(256)
__global__ void k_gemm_bf(const __nv_bfloat16* __restrict__ A,
                          const __nv_bfloat16* __restrict__ W,
                          void* __restrict__ CoutV, int N, int Kd)
{
    extern __shared__ __align__(16) unsigned smbuf[];
    unsigned* As = smbuf;               // STG tiles
    unsigned* Bs = smbuf + STG*TILEU;   // STG tiles
    const int m0 = blockIdx.y * 128, n0 = blockIdx.x * 128;
    const int tid  = threadIdx.x;
    const int warp = tid >> 5, lane = tid & 31;
    const int wm = (warp & 3) * 32;
    const int wn = (warp >> 2) * 64;
    const int grp = lane >> 2, tig = lane & 3;
    const int l15 = lane & 15, lhi = (lane >> 4) * 4;

    float acc[2][8][4];
    #pragma unroll
    for (int mt = 0; mt < 2; mt++)
        #pragma unroll
        for (int nt = 0; nt < 8; nt++)
            #pragma unroll
            for (int q = 0; q < 4; q++) acc[mt][nt][q] = 0.f;

    const int NC = Kd >> 5;

    auto preload = [&](int c) {
        unsigned* Ab = As + (c % STG) * TILEU;
        unsigned* Bb = Bs + (c % STG) * TILEU;
        #pragma unroll
        for (int i = 0; i < 2; i++) {
            int id = tid + i*256;
            int rr = id >> 2, qq = id & 3;
            cpasync16(smaddr(Ab + rr*GP + qq*4),
                      A + (size_t)(m0 + rr)*Kd + c*32 + qq*8, 16);
        }
        #pragma unroll
        for (int i = 0; i < 2; i++) {
            int id = tid + i*256;
            int rr = id >> 2, qq = id & 3;
            int valid = (n0 + rr < N);
            cpasync16(smaddr(Bb + rr*GP + qq*4),
                      W + (size_t)(valid ? (n0 + rr) : 0)*Kd + c*32 + qq*8,
                      valid ? 16 : 0);
        }
        asm volatile("cp.async.commit_group;");
    };

    preload(0);
    if (NC > 1) preload(1);
    for (int c = 0; c < NC; c++) {
        if (c + 2 < NC) { preload(c + 2); asm volatile("cp.async.wait_group 2;"); }
        else if (c + 1 < NC) { asm volatile("cp.async.wait_group 1;"); }
        else { asm volatile("cp.async.wait_group 0;"); }
        __syncthreads();
        const unsigned* Ab = As + (c % STG) * TILEU;
        const unsigned* Bb = Bs + (c % STG) * TILEU;
        #pragma unroll
        for (int ks = 0; ks < 2; ks++) {
            int kc = ks * 8;
            unsigned af[2][4], bf[8][2];
            #pragma unroll
            for (int mt = 0; mt < 2; mt++)
                ldsm4(af[mt][0], af[mt][1], af[mt][2], af[mt][3],
                      smaddr(Ab + (wm + mt*16 + l15)*GP + kc + lhi));
            #pragma unroll
            for (int pr = 0; pr < 4; pr++)
                ldsm4(bf[2*pr][0], bf[2*pr+1][0], bf[2*pr][1], bf[2*pr+1][1],
                      smaddr(Bb + (wn + pr*16 + l15)*GP + kc + lhi));
            #pragma unroll
            for (int mt = 0; mt < 2; mt++)
                #pragma unroll
                for (int nt = 0; nt < 8; nt++)
                    mma_bf16(acc[mt][nt], af[mt], bf[nt]);
        }
        __syncthreads();
    }

    // epilogue: c0,c1 -> (grp, 2tig); c2,c3 -> (grp+8, 2tig)
    #pragma unroll
    for (int mt = 0; mt < 2; mt++) {
        #pragma unroll
        for (int nt = 0; nt < 8; nt++) {
            int m = m0 + wm + mt*16 + grp;
            int n = n0 + wn + nt*8 + 2*tig;
            if (n < N) {
                if (BF16OUT) {
                    __nv_bfloat16* Cb = (__nv_bfloat16*)CoutV;
                    *(__nv_bfloat162*)(Cb + (size_t)m*N + n) =
                        __floats2bfloat162_rn(acc[mt][nt][0], acc[mt][nt][1]);
                    *(__nv_bfloat162*)(Cb + (size_t)(m+8)*N + n) =
                        __floats2bfloat162_rn(acc[mt][nt][2], acc[mt][nt][3]);
                } else {
                    float* Cf = (float*)CoutV;
                    float2* p0 = (float2*)(Cf + (size_t)m*N + n);
                    float2* p1 = (float2*)(Cf + (size_t)(m+8)*N + n);
                    if (ACC) {
                        float2 v0 = *p0, v1 = *p1;
                        v0.x += acc[mt][nt][0]; v0.y += acc[mt][nt][1];
                        v1.x += acc[mt][nt][2]; v1.y += acc[mt][nt][3];
                        *p0 = v0; *p1 = v1;
                    } else {
                        *p0 = make_float2(acc[mt][nt][0], acc[mt][nt][1]);
                        *p1 = make_float2(acc[mt][nt][2], acc[mt][nt][3]);
                    }
                }
            }
        }
    }
}

// ---------------- depthwise causal conv (K=4) + silu, 4 tokens/thread --------
__global__ void k_conv(const float* __restrict__ w, const float* __restrict__ bias) {
    int idx = blockIdx.x * 256 + threadIdx.x;      // over Mtok*DIdim/4
    int d = idx & (DIdim - 1);
    int mg = idx >> 9;                              // token group of 4
    int m0 = mg * 4;
    int l0 = m0 & (Lseq - 1);
    float xv[7];
    #pragma unroll
    for (int k = 0; k < 7; k++) {
        int l = l0 - 3 + k;
        xv[k] = (l >= 0 && k < 3 + 4)
              ? ((l0 - 3 + k >= 0)
                 ? __bfloat162float(g_xz_bf[(size_t)(m0 - 3 + k)*(2*DIdim) + d]) : 0.f)
              : 0.f;
        if (l < 0) xv[k] = 0.f;
    }
    const float* wd = w + d*4;
    float w0 = wd[0], w1 = wd[1], w2 = wd[2], w3 = wd[3];
    float bb = bias[d];
    #pragma unroll
    for (int j = 0; j < 4; j++) {
        float s = bb + w0*xv[j] + w1*xv[j+1] + w2*xv[j+2] + w3*xv[j+3];
        g_xc_bf[(size_t)(m0 + j)*DIdim + d] = __float2bfloat16(siluf(s));
    }
}

// ---------------- selective scan (dt fused, deferred reduction, gated) -------
__launch_bounds__(256)
__global__ void k_scan2(const float* __restrict__ alog, const float* __restrict__ Dp,
                        const float* __restrict__ dw, const float* __restrict__ db) {
    __shared__ __align__(16) float s_dt[32][16], s_x[32][16], s_B[32][16], s_C[32][16];
    __shared__ __align__(16) float s_P[32][16];
    __shared__ __align__(16) float s_p[32][16][16];
    __shared__ float s_dw[16][17];
    __shared__ float s_db[16], s_D[16];
    int b  = blockIdx.x >> 5;
    int d0 = (blockIdx.x & 31) << 4;
    int tid = threadIdx.x;
    int n  = tid & 15, dg = tid >> 4;
    int d  = d0 + dg;
    float Ad = -__expf(alog[d*DSdim + n]);
    if (tid < 16) { s_D[tid] = Dp[d0 + tid]; s_db[tid] = db[d0 + tid]; }
    s_dw[tid >> 4][tid & 15] = dw[(d0 + (tid >> 4))*16 + (tid & 15)];
    float h = 0.f;
    float rP[2], rx[2], rB[2], rC[2];

    auto ldc = [&](int l0) {
        #pragma unroll
        for (int it = 0; it < 2; it++) {
            int i = tid + it*256;
            int l = i >> 4, j = i & 15;
            size_t t = (size_t)(b*Lseq + l0 + l);
            rP[it] = g_proj[t*48 + j];
            rx[it] = __bfloat162float(g_xc_bf[t*DIdim + d0 + j]);
            rB[it] = g_proj[t*48 + 16 + j];
            rC[it] = g_proj[t*48 + 32 + j];
        }
    };
    auto stc = [&]() {
        #pragma unroll
        for (int it = 0; it < 2; it++) {
            int i = tid + it*256;
            int l = i >> 4, j = i & 15;
            s_P[l][j] = rP[it]; s_x[l][j] = rx[it];
            s_B[l][j] = rB[it]; s_C[l][j] = rC[it];
        }
    };
    auto dtcalc = [&]() {
        #pragma unroll
        for (int it = 0; it < 2; it++) {
            int i = tid + it*256;
            int l = i >> 4, j = i & 15;
            float s = s_db[j];
            #pragma unroll
            for (int r = 0; r < 16; r++) s += s_P[l][r] * s_dw[j][r];
            s_dt[l][j] = (s > 15.f) ? s : __logf(1.f + __expf(s));
        }
    };

    ldc(0); stc(); __syncthreads(); dtcalc(); __syncthreads();
    for (int ch = 0; ch < 32; ch++) {
        int l0 = ch * 32;
        if (ch < 31) ldc(l0 + 32);
        #pragma unroll 8
        for (int l = 0; l < 32; l++) {
            float dtv = s_dt[l][dg];
            float w = __expf(dtv * Ad);
            float u = (dtv * s_x[l][dg]) * s_B[l][n];
            h = h * w + u;
            s_p[l][dg][n] = h * s_C[l][n];
        }
        __syncthreads();
        #pragma unroll
        for (int it = 0; it < 2; it++) {
            int i = tid + it*256;
            int l = i >> 4, g = i & 15;
            float4 p0 = *(float4*)&s_p[l][g][0];
            float4 p1 = *(float4*)&s_p[l][g][4];
            float4 p2 = *(float4*)&s_p[l][g][8];
            float4 p3 = *(float4*)&s_p[l][g][12];
            float s = ((p0.x+p0.y)+(p0.z+p0.w)) + ((p1.x+p1.y)+(p1.z+p1.w))
                    + ((p2.x+p2.y)+(p2.z+p2.w)) + ((p3.x+p3.y)+(p3.z+p3.w));
            size_t t = (size_t)(b*Lseq + l0 + l);
            float yv = s + s_x[l][g] * s_D[g];
            float z = __bfloat162float(g_xz_bf[t*(2*DIdim) + DIdim + d0 + g]);
            yv *= z / (1.f + __expf(-z));
            g_y_bf[t*DIdim + d0 + g] = __float2bfloat16(yv);
        }
        __syncthreads();
        if (ch < 31) { stc(); __syncthreads(); dtcalc(); __syncthreads(); }
    }
}

// ---------------- SE: zero, pool, MLP ----------------------------------------
__global__ void k_zero_g0() {
    int i = blockIdx.x * 256 + threadIdx.x;
    if (i < Bsz*Cch) g_g0[i] = 0.f;
}
__global__ void k_pool() {
    int b = blockIdx.x >> 2, q = blockIdx.x & 3;
    int c = threadIdx.x;
    float s = 0.f;
    for (int l = q*256; l < q*256 + 256; l++)
        s += g_xs[(size_t)(b*Lseq + l)*Cch + c];
    atomicAdd(&g_g0[b*Cch + c], s * (1.f/1024.f));
}
__global__ void k_se(const float* __restrict__ w1, const float* __restrict__ b1,
                     const float* __restrict__ w2, const float* __restrict__ b2) {
    __shared__ float sg[Bsz*Cch];
    __shared__ float sh[Bsz*64];
    int t = threadIdx.x;
    for (int i = t; i < Bsz*Cch; i += 256) sg[i] = g_g0[i];
    __syncthreads();
    for (int i = t; i < Bsz*64; i += 256) {
        int b = i >> 6, j = i & 63;
        float s = b1[j];
        const float* wr = w1 + j*256;
        const float* gr = sg + b*256;
        #pragma unroll 8
        for (int c = 0; c < 256; c++) s += gr[c] * wr[c];
        sh[i] = fmaxf(s, 0.f);
    }
    __syncthreads();
    for (int i = t; i < Bsz*Cch; i += 256) {
        int b = i >> 8, c = i & 255;
        float s = b2[c];
        const float* wr = w2 + c*64;
        const float* hr = sh + b*64;
        #pragma unroll 8
        for (int j = 0; j < 64; j++) s += hr[j] * wr[j];
        g_gate[i] = 1.f / (1.f + __expf(-s));
    }
}

// ---------------- y = xo*g + residual, transposed to (b,c,l) -----------------
__global__ void k_ybn(const float* __restrict__ x) {
    __shared__ float tile[32][33];
    int b = blockIdx.z, c0 = blockIdx.y * 32, l0 = blockIdx.x * 32;
    int tx = threadIdx.x, ty = threadIdx.y;
    #pragma unroll
    for (int i = ty; i < 32; i += 8)
        tile[i][tx] = g_xs[(size_t)(b*Lseq + l0 + i)*Cch + c0 + tx];   // tile[l][c]
    __syncthreads();
    #pragma unroll
    for (int i = ty; i < 32; i += 8) {
        int c = c0 + i;
        size_t o = (size_t)(b*Cch + c)*Lseq + l0 + tx;
        g_ybn[o] = tile[tx][i] * g_gate[b*Cch + c] + x[o];
    }
}

// ---------------- batchnorm stats + apply ------------------------------------
__global__ void k_bnstats() {
    int c = blockIdx.x, t = threadIdx.x;
    float s = 0.f, s2 = 0.f;
    for (int b = 0; b < Bsz; b++)
        for (int l = t; l < Lseq; l += 256) {
            float v = g_ybn[(size_t)(b*Cch + c)*Lseq + l];
            s += v; s2 += v * v;
        }
    __shared__ float sh[256], sh2[256];
    sh[t] = s; sh2[t] = s2;
    __syncthreads();
    #pragma unroll
    for (int st = 128; st > 0; st >>= 1) {
        if (t < st) { sh[t] += sh[t + st]; sh2[t] += sh2[t + st]; }
        __syncthreads();
    }
    if (t == 0) {
        float mu  = sh[0] * (1.f/8192.f);
        float var = sh2[0] * (1.f/8192.f) - mu*mu;
        g_stats[c]       = mu;
        g_stats[Cch + c] = rsqrtf(var + 1e-5f);
    }
}
__global__ void k_bnapply(float* __restrict__ out, const float* __restrict__ bw,
                          const float* __restrict__ bb) {
    int idx = blockIdx.x * 256 + threadIdx.x;   // Bsz*Cch*Lseq
    int c = (idx >> 10) & 255;
    out[idx] = (g_ybn[idx] - g_stats[c]) * g_stats[Cch + c] * bw[c] + bb[c];
}

// ---------------- host driver ------------------------------------------------
extern "C" void kernel_launch(void* const* d_in, const int* in_sizes, int n_in,
                              void* d_out, int out_size)
{
    const float* x         = (const float*)d_in[0];
    const float* ln_w      = (const float*)d_in[1];
    const float* ln_b      = (const float*)d_in[2];
    const float* in_proj_w = (const float*)d_in[3];
    const float* conv_w    = (const float*)d_in[4];
    const float* conv_b    = (const float*)d_in[5];
    const float* x_proj_w  = (const float*)d_in[6];
    const float* dt_proj_w = (const float*)d_in[7];
    const float* dt_proj_b = (const float*)d_in[8];
    const float* A_log     = (const float*)d_in[9];
    const float* Dp        = (const float*)d_in[10];
    const float* out_proj_w= (const float*)d_in[11];
    const float* se_w1     = (const float*)d_in[12];
    const float* se_b1     = (const float*)d_in[13];
    const float* se_w2     = (const float*)d_in[14];
    const float* se_b2     = (const float*)d_in[15];
    const float* bn_w      = (const float*)d_in[16];
    const float* bn_b      = (const float*)d_in[17];
    float* out = (float*)d_out;

    void *p;
    cudaGetSymbolAddress(&p, g_xn_bf);   __nv_bfloat16* pxn  = (__nv_bfloat16*)p;
    cudaGetSymbolAddress(&p, g_xz_bf);   __nv_bfloat16* pxzb = (__nv_bfloat16*)p;
    cudaGetSymbolAddress(&p, g_xc_bf);   __nv_bfloat16* pxcb = (__nv_bfloat16*)p;
    cudaGetSymbolAddress(&p, g_proj);    float* pproj = (float*)p;
    cudaGetSymbolAddress(&p, g_y_bf);    __nv_bfloat16* pyb  = (__nv_bfloat16*)p;
    cudaGetSymbolAddress(&p, g_xs);      float* pxs  = (float*)p;
    cudaGetSymbolAddress(&p, g_win_bf);  __nv_bfloat16* pwin = (__nv_bfloat16*)p;
    cudaGetSymbolAddress(&p, g_wx_bf);   __nv_bfloat16* pwx  = (__nv_bfloat16*)p;
    cudaGetSymbolAddress(&p, g_wout_bf); __nv_bfloat16* pwo  = (__nv_bfloat16*)p;

    cudaFuncSetAttribute(k_gemm_bf<false, true>,
                         cudaFuncAttributeMaxDynamicSharedMemorySize, GEMM_SMEM);
    cudaFuncSetAttribute(k_gemm_bf<false, false>,
                         cudaFuncAttributeMaxDynamicSharedMemorySize, GEMM_SMEM);
    cudaFuncSetAttribute(k_gemm_bf<true, false>,
                         cudaFuncAttributeMaxDynamicSharedMemorySize, GEMM_SMEM);

    k_cvtw<<<(NLAYER*2*DIdim*Cch + 255)/256, 256>>>(in_proj_w, x_proj_w, out_proj_w);
    dim3 tb(32, 8);
    k_transpose_in<<<dim3(32, 8, Bsz), tb>>>(x);

    for (int i = 0; i < NLAYER; i++) {
        k_ln<<<Mtok/8, 256>>>(ln_w + i*Cch, ln_b + i*Cch);
        k_gemm_bf<false, true><<<dim3(8, 64), 256, GEMM_SMEM>>>(
            pxn, pwin + (size_t)i*2*DIdim*Cch, pxzb, 2*DIdim, Cch);
        k_conv<<<Mtok*DIdim/1024, 256>>>(conv_w + i*DIdim*4, conv_b + i*DIdim);
        k_gemm_bf<false, false><<<dim3(1, 64), 256, GEMM_SMEM>>>(
            pxcb, pwx + (size_t)i*48*DIdim, pproj, 48, DIdim);
        k_scan2<<<256, 256>>>(A_log + i*DIdim*DSdim, Dp + i*DIdim,
                              dt_proj_w + i*DIdim*16, dt_proj_b + i*DIdim);
        k_gemm_bf<true, false><<<dim3(2, 64), 256, GEMM_SMEM>>>(
            pyb, pwo + (size_t)i*Cch*DIdim, pxs, Cch, DIdim);
    }

    k_zero_g0<<<8, 256>>>();
    k_pool<<<Bsz*4, 256>>>();
    k_se<<<1, 256>>>(se_w1, se_b1, se_w2, se_b2);
    k_ybn<<<dim3(32, 8, Bsz), tb>>>(x);
    k_bnstats<<<Cch, 256>>>();
    k_bnapply<<<Bsz*Cch*Lseq/256, 256>>>(out, bn_w, bn_b);

    (void)in_sizes; (void)n_in; (void)out_size;
}